// round 4
// baseline (speedup 1.0000x reference)
#include <cuda_runtime.h>
#include <math.h>

#define NA 15000
#define NE 300000
#define FF 128
#define NRBF 20
#define NL 3
#define CUTOFF 5.0f
#define PI_F 3.14159265358979f

typedef unsigned long long u64;

// ---------------- static scratch (no allocations allowed) ----------------
__device__ float4 g_dirf[NE];          // sorted: (dir.x, dir.y, dir.z, fcut)
__device__ float g_phis[NE * NRBF];    // sorted: phi * fcut
__device__ int   g_js[NE];             // sorted: idx_j
__device__ int   g_perm[NE];           // edge -> sorted pos
__device__ float g_x[NA * 384];
__device__ float g_h[NA * 128];
__device__ float g_ctx[NA * 256];
__device__ float g_mumix[NA * 3 * 256];
__device__ float g_muA[NA * 384];
__device__ float g_muB[NA * 384];
// CSR over idx_i
__device__ int g_cnt[NA];
__device__ int g_rowptr[NA + 1];
__device__ int g_head[NA];

// ---------------- CSR build ----------------
__global__ void init_kernel(const int* __restrict__ z, const float* __restrict__ emb,
                            float* __restrict__ q) {
    int i = blockIdx.x * blockDim.x + threadIdx.x;
    if (i >= NA * 384) return;
    g_muA[i] = 0.0f;
    if (i < NA * FF) {
        int a = i >> 7, f = i & 127;
        q[i] = emb[z[a] * FF + f];
    }
    if (i < NA) g_cnt[i] = 0;
}

__global__ void hist_kernel(const int* __restrict__ idx_i) {
    int e = blockIdx.x * blockDim.x + threadIdx.x;
    if (e < NE) atomicAdd(&g_cnt[idx_i[e]], 1);
}

#define SCAN_T 1024
#define SCAN_CH ((NA + SCAN_T - 1) / SCAN_T)
__global__ void __launch_bounds__(SCAN_T) scan_kernel() {
    __shared__ int sh[SCAN_T];
    int t = threadIdx.x;
    int start = t * SCAN_CH;
    int s = 0;
#pragma unroll
    for (int k = 0; k < SCAN_CH; k++) {
        int i = start + k;
        if (i < NA) s += g_cnt[i];
    }
    sh[t] = s;
    __syncthreads();
    for (int off = 1; off < SCAN_T; off <<= 1) {
        int v = (t >= off) ? sh[t - off] : 0;
        __syncthreads();
        sh[t] += v;
        __syncthreads();
    }
    int base = (t == 0) ? 0 : sh[t - 1];
#pragma unroll
    for (int k = 0; k < SCAN_CH; k++) {
        int i = start + k;
        if (i < NA) {
            g_rowptr[i] = base;
            g_head[i] = base;
            base += g_cnt[i];
        }
    }
    if (t == SCAN_T - 1) g_rowptr[NA] = base;
}

__global__ void scatter_kernel(const int* __restrict__ idx_i, const int* __restrict__ idx_j) {
    int e = blockIdx.x * blockDim.x + threadIdx.x;
    if (e >= NE) return;
    int pos = atomicAdd(&g_head[idx_i[e]], 1);
    g_perm[e] = pos;
    g_js[pos] = idx_j[e];
}

// ---------------- edge geometry written at sorted positions ----------------
__global__ void geom_kernel(const float* __restrict__ rij) {
    int e = blockIdx.x * blockDim.x + threadIdx.x;
    if (e >= NE) return;
    int p = g_perm[e];
    float r0 = rij[e * 3 + 0], r1 = rij[e * 3 + 1], r2 = rij[e * 3 + 2];
    float d = sqrtf(r0 * r0 + r1 * r1 + r2 * r2);
    float inv = 1.0f / d;
    float fc = (d < CUTOFF) ? 0.5f * (cosf(d * PI_F / CUTOFF) + 1.0f) : 0.0f;
    g_dirf[p] = make_float4(r0 * inv, r1 * inv, r2 * inv, fc);
    const float width = CUTOFF / (NRBF - 1);
    const float coeff = -0.5f / (width * width);
#pragma unroll
    for (int k = 0; k < NRBF; k++) {
        float t = d - width * k;
        g_phis[p * NRBF + k] = expf(coeff * t * t) * fc;
    }
}

// ---------------- atomic-free edge kernel (CSR, per-atom ownership) ----------------
__global__ void __launch_bounds__(128) edge_kernel(const float* __restrict__ W,
                                                   const float* __restrict__ b,
                                                   int layer,
                                                   const float* __restrict__ mu_in,
                                                   float* __restrict__ mu_out,
                                                   float* __restrict__ q) {
    int f = threadIdx.x;
    float w0[NRBF], w1[NRBF], w2[NRBF];
#pragma unroll
    for (int k = 0; k < NRBF; k++) {
        const float* row = W + k * (NL * 384) + layer * 384;
        w0[k] = row[f];
        w1[k] = row[128 + f];
        w2[k] = row[256 + f];
    }
    float b0 = b[layer * 384 + f];
    float b1v = b[layer * 384 + 128 + f];
    float b2v = b[layer * 384 + 256 + f];

    for (int a = blockIdx.x; a < NA; a += gridDim.x) {
        int s = g_rowptr[a], eend = g_rowptr[a + 1];
        float accq = 0.f, acc0 = 0.f, acc1 = 0.f, acc2 = 0.f;
        int jn = (s < eend) ? __ldg(g_js + s) : 0;
#pragma unroll 2
        for (int t = s; t < eend; t++) {
            int j = jn;
            jn = (t + 1 < eend) ? __ldg(g_js + t + 1) : 0;
            const float4* p4 = (const float4*)(g_phis + t * NRBF);
            float4 P0 = __ldg(p4 + 0), P1 = __ldg(p4 + 1), P2 = __ldg(p4 + 2),
                   P3 = __ldg(p4 + 3), P4 = __ldg(p4 + 4);
            float4 df = __ldg(g_dirf + t);
            const float* xj = g_x + j * 384;
            const float* mj = mu_in + j * 384;
            float x0 = __ldg(xj + f), x1 = __ldg(xj + 128 + f), x2 = __ldg(xj + 256 + f);
            float m0 = __ldg(mj + f), m1 = __ldg(mj + 128 + f), m2 = __ldg(mj + 256 + f);
            float ph[NRBF] = {P0.x, P0.y, P0.z, P0.w, P1.x, P1.y, P1.z, P1.w,
                              P2.x, P2.y, P2.z, P2.w, P3.x, P3.y, P3.z, P3.w,
                              P4.x, P4.y, P4.z, P4.w};
            float a0 = b0 * df.w, a1 = b1v * df.w, a2 = b2v * df.w;
#pragma unroll
            for (int k = 0; k < NRBF; k++) {
                a0 += ph[k] * w0[k];
                a1 += ph[k] * w1[k];
                a2 += ph[k] * w2[k];
            }
            float dmuR = a1 * x1;
            float dmm  = a2 * x2;
            accq += a0 * x0;
            acc0 += dmuR * df.x + dmm * m0;
            acc1 += dmuR * df.y + dmm * m1;
            acc2 += dmuR * df.z + dmm * m2;
        }
        q[a * 128 + f] += accq;
        mu_out[a * 384 + f]       = mu_in[a * 384 + f] + acc0;
        mu_out[a * 384 + 128 + f] = mu_in[a * 384 + 128 + f] + acc1;
        mu_out[a * 384 + 256 + f] = mu_in[a * 384 + 256 + f] + acc2;
    }
}

// ---------------- f32x2 helpers ----------------
__device__ __forceinline__ u64 pack_dup(float a) {
    u64 r;
    asm("mov.b64 %0, {%1, %1};" : "=l"(r) : "f"(a));
    return r;
}
__device__ __forceinline__ void fma2(u64& d, u64 a, u64 b) {
    asm("fma.rn.f32x2 %0, %1, %2, %0;" : "+l"(d) : "l"(a), "l"(b));
}
__device__ __forceinline__ void unpack2(float& lo, float& hi, u64 v) {
    asm("mov.b64 {%0, %1}, %2;" : "=f"(lo), "=f"(hi) : "l"(v));
}

// ---------------- SGEMM: C = act(A@B + bias), FFMA2 inner loop ----------------
// TM rows per block, 128 cols per block, 256 threads, K % 8 == 0, N % 128 == 0.
template <int TM>
__global__ void __launch_bounds__(256) sgemm_kernel(const float* __restrict__ A,
                                                    const float* __restrict__ B,
                                                    const float* __restrict__ bias,
                                                    float* __restrict__ C,
                                                    int M, int N, int K, int act) {
    constexpr int RT = TM / 16;  // rows per thread (8 or 4)
    __shared__ float As[8][TM];
    __shared__ float Bs[8][128];
    int tid = threadIdx.x;
    int row0 = blockIdx.y * TM, col0 = blockIdx.x * 128;
    int tx = tid & 15, ty = tid >> 4;
    int bK = tid >> 5, bN = (tid & 31) << 2;

    u64 acc[RT][4];
    u64 zero = pack_dup(0.0f);
#pragma unroll
    for (int i = 0; i < RT; i++)
#pragma unroll
        for (int j = 0; j < 4; j++) acc[i][j] = zero;

    for (int k0 = 0; k0 < K; k0 += 8) {
        if (TM == 128) {
            int aRow = tid >> 1, aK = (tid & 1) << 2;
            float4 av = (row0 + aRow < M)
                            ? *(const float4*)(A + (size_t)(row0 + aRow) * K + k0 + aK)
                            : make_float4(0.f, 0.f, 0.f, 0.f);
            As[aK + 0][aRow] = av.x;
            As[aK + 1][aRow] = av.y;
            As[aK + 2][aRow] = av.z;
            As[aK + 3][aRow] = av.w;
        } else {
            int aRow = tid >> 2, aK = (tid & 3) << 1;
            float2 av = (row0 + aRow < M)
                            ? *(const float2*)(A + (size_t)(row0 + aRow) * K + k0 + aK)
                            : make_float2(0.f, 0.f);
            As[aK + 0][aRow] = av.x;
            As[aK + 1][aRow] = av.y;
        }
        *(float4*)&Bs[bK][bN] = *(const float4*)(B + (size_t)(k0 + bK) * N + col0 + bN);
        __syncthreads();
#pragma unroll
        for (int kk = 0; kk < 8; kk++) {
            u64 ap[RT];
#pragma unroll
            for (int i = 0; i < RT; i++) ap[i] = pack_dup(As[kk][ty * RT + i]);
            u64 bp[4];
#pragma unroll
            for (int j = 0; j < 4; j++) bp[j] = *(const u64*)&Bs[kk][tx * 8 + j * 2];
#pragma unroll
            for (int i = 0; i < RT; i++)
#pragma unroll
                for (int j = 0; j < 4; j++) fma2(acc[i][j], ap[i], bp[j]);
        }
        __syncthreads();
    }
    float bias8[8];
#pragma unroll
    for (int j = 0; j < 8; j++) bias8[j] = bias[col0 + tx * 8 + j];
#pragma unroll
    for (int i = 0; i < RT; i++) {
        int r = row0 + ty * RT + i;
        if (r < M) {
            float out[8];
#pragma unroll
            for (int j = 0; j < 4; j++) {
                float lo, hi;
                unpack2(lo, hi, acc[i][j]);
                out[j * 2] = lo;
                out[j * 2 + 1] = hi;
            }
#pragma unroll
            for (int j = 0; j < 8; j++) {
                float v = out[j] + bias8[j];
                if (act) v = v / (1.0f + expf(-v));
                out[j] = v;
            }
            *(float4*)(C + (size_t)r * N + col0 + tx * 8) = *(float4*)&out[0];
            *(float4*)(C + (size_t)r * N + col0 + tx * 8 + 4) = *(float4*)&out[4];
        }
    }
}

// ---------------- ctx = [q, ||mu_V||] ----------------
__global__ void ctx_kernel(const float* __restrict__ q) {
    int i = blockIdx.x * blockDim.x + threadIdx.x;
    if (i >= NA * FF) return;
    int a = i >> 7, f = i & 127;
    float v0 = g_mumix[(a * 3 + 0) * 256 + f];
    float v1 = g_mumix[(a * 3 + 1) * 256 + f];
    float v2 = g_mumix[(a * 3 + 2) * 256 + f];
    g_ctx[a * 256 + f] = q[i];
    g_ctx[a * 256 + 128 + f] = sqrtf(v0 * v0 + v1 * v1 + v2 * v2);
}

// ---------------- intra update of q and mu ----------------
__global__ void update_kernel(float* __restrict__ q, float* __restrict__ mu) {
    int i = blockIdx.x * blockDim.x + threadIdx.x;
    if (i >= NA * FF) return;
    int a = i >> 7, f = i & 127;
    float s = 0.0f;
    float xmu = g_x[a * 384 + 128 + f];
#pragma unroll
    for (int d = 0; d < 3; d++) {
        float mv = g_mumix[(a * 3 + d) * 256 + f];
        float mw = g_mumix[(a * 3 + d) * 256 + 128 + f];
        s += mv * mw;
        mu[(a * 3 + d) * 128 + f] += xmu * mw;
    }
    q[i] += g_x[a * 384 + f] + g_x[a * 384 + 256 + f] * s;
}

// ---------------- launcher ----------------
extern "C" void kernel_launch(void* const* d_in, const int* in_sizes, int n_in,
                              void* d_out, int out_size) {
    const float* r_ij      = (const float*)d_in[0];
    const float* embedding = (const float*)d_in[1];
    const float* filt_W    = (const float*)d_in[2];
    const float* filt_b    = (const float*)d_in[3];
    const float* inter_W1  = (const float*)d_in[4];
    const float* inter_b1  = (const float*)d_in[5];
    const float* inter_W2  = (const float*)d_in[6];
    const float* inter_b2  = (const float*)d_in[7];
    const float* mix_W     = (const float*)d_in[8];
    const float* mix_b     = (const float*)d_in[9];
    const float* intra_W1  = (const float*)d_in[10];
    const float* intra_b1  = (const float*)d_in[11];
    const float* intra_W2  = (const float*)d_in[12];
    const float* intra_b2  = (const float*)d_in[13];
    const int*   z         = (const int*)d_in[14];
    const int*   idx_i     = (const int*)d_in[15];
    const int*   idx_j     = (const int*)d_in[16];

    float* q      = (float*)d_out;
    float* mu_fin = q + (size_t)NA * FF;

    void *p_h, *p_x, *p_ctx, *p_mumix, *p_muA, *p_muB;
    cudaGetSymbolAddress(&p_h, g_h);
    cudaGetSymbolAddress(&p_x, g_x);
    cudaGetSymbolAddress(&p_ctx, g_ctx);
    cudaGetSymbolAddress(&p_mumix, g_mumix);
    cudaGetSymbolAddress(&p_muA, g_muA);
    cudaGetSymbolAddress(&p_muB, g_muB);
    float* hbuf  = (float*)p_h;
    float* xbuf  = (float*)p_x;
    float* ctx   = (float*)p_ctx;
    float* mumix = (float*)p_mumix;
    float* muA   = (float*)p_muA;
    float* muB   = (float*)p_muB;

    init_kernel<<<(NA * 384 + 255) / 256, 256>>>(z, embedding, q);
    hist_kernel<<<(NE + 255) / 256, 256>>>(idx_i);
    scan_kernel<<<1, SCAN_T>>>();
    scatter_kernel<<<(NE + 255) / 256, 256>>>(idx_i, idx_j);
    geom_kernel<<<(NE + 255) / 256, 256>>>(r_ij);

    // mu buffer schedule: L0: A(zero)->B, L1: B->A, L2: A->d_out
    float* mu_in_l[NL]  = {muA, muB, muA};
    float* mu_out_l[NL] = {muB, muA, mu_fin};

    for (int l = 0; l < NL; l++) {
        float* mi = mu_in_l[l];
        float* mo = mu_out_l[l];
        // h = silu(q @ W1 + b1)   (N=128 -> TM=64, 235 blocks)
        sgemm_kernel<64><<<dim3(1, (NA + 63) / 64), 256>>>(
            q, inter_W1 + (size_t)l * 128 * 128, inter_b1 + l * 128, hbuf, NA, 128, 128, 1);
        // x = h @ W2 + b2
        sgemm_kernel<128><<<dim3(3, (NA + 127) / 128), 256>>>(
            hbuf, inter_W2 + (size_t)l * 128 * 384, inter_b2 + l * 384, xbuf, NA, 384, 128, 0);
        // fused filters + edge messages (atomic-free, CSR, sorted records)
        edge_kernel<<<1875, 128>>>(filt_W, filt_b, l, mi, mo, q);
        // mu_mix = mu @ mix_W + mix_b   (45000 x 256)
        sgemm_kernel<128><<<dim3(2, (NA * 3 + 127) / 128), 256>>>(
            mo, mix_W + (size_t)l * 128 * 256, mix_b + l * 256, mumix, NA * 3, 256, 128, 0);
        // ctx = [q, ||mu_V||]
        ctx_kernel<<<(NA * FF + 255) / 256, 256>>>(q);
        // h = silu(ctx @ intra_W1 + b1)  (N=128 -> TM=64)
        sgemm_kernel<64><<<dim3(1, (NA + 63) / 64), 256>>>(
            ctx, intra_W1 + (size_t)l * 256 * 128, intra_b1 + l * 128, hbuf, NA, 128, 256, 1);
        // x = h @ intra_W2 + b2
        sgemm_kernel<128><<<dim3(3, (NA + 127) / 128), 256>>>(
            hbuf, intra_W2 + (size_t)l * 128 * 384, intra_b2 + l * 384, xbuf, NA, 384, 128, 0);
        // q += dq_intra + dqmu_intra ; mu += dmu_intra
        update_kernel<<<(NA * FF + 255) / 256, 256>>>(q, mo);
    }
}

// round 6
// speedup vs baseline: 1.2081x; 1.2081x over previous
#include <cuda_runtime.h>
#include <cuda_bf16.h>
#include <math.h>
#include <stdint.h>

#define NA 15000
#define NE 300000
#define FF 128
#define NRBF 20
#define NL 3
#define CUTOFF 5.0f
#define PI_F 3.14159265358979f

// =================== static scratch ===================
__device__ float4 g_dirf[NE];         // (dir.xyz, fcut)
__device__ float g_phis[NE * NRBF];   // phi * fcut
__device__ float g_x[NA * 384];
__device__ float g_h[NA * 128];
__device__ float g_ctx[NA * 256];
__device__ float g_mumix[NA * 3 * 256];
__device__ float g_dmu[NA * 3 * 128];
// bf16 split activations (A) and transposed split weights (B)
#define AMAX (45000 * 128)
__device__ __nv_bfloat16 g_Ahi[AMAX];
__device__ __nv_bfloat16 g_Alo[AMAX];
#define WL 180224  // per-layer transposed-weight elems
__device__ __nv_bfloat16 g_Bhi[NL * WL];
__device__ __nv_bfloat16 g_Blo[NL * WL];
// offsets inside a WL block: w1t 0, w2t 16384, mixt 65536, iw1t 98304, iw2t 131072

// =================== small kernels ===================
__global__ void geom_kernel(const float* __restrict__ rij) {
    int e = blockIdx.x * blockDim.x + threadIdx.x;
    if (e >= NE) return;
    float r0 = rij[e * 3 + 0], r1 = rij[e * 3 + 1], r2 = rij[e * 3 + 2];
    float d = sqrtf(r0 * r0 + r1 * r1 + r2 * r2);
    float inv = 1.0f / d;
    float fc = (d < CUTOFF) ? 0.5f * (cosf(d * PI_F / CUTOFF) + 1.0f) : 0.0f;
    g_dirf[e] = make_float4(r0 * inv, r1 * inv, r2 * inv, fc);
    const float width = CUTOFF / (NRBF - 1);
    const float coeff = -0.5f / (width * width);
#pragma unroll
    for (int k = 0; k < NRBF; k++) {
        float t = d - width * k;
        g_phis[e * NRBF + k] = expf(coeff * t * t) * fc;
    }
}

__global__ void init_kernel(const int* __restrict__ z, const float* __restrict__ emb,
                            float* __restrict__ q, float* __restrict__ mu) {
    int i = blockIdx.x * blockDim.x + threadIdx.x;
    if (i >= NA * 384) return;
    mu[i] = 0.0f;
    g_dmu[i] = 0.0f;
    if (i < NA * FF) {
        int a = i >> 7, f = i & 127;
        q[i] = emb[z[a] * FF + f];
    }
}

// transpose+split weight: src (K,N) fp32 -> dst[n*K+k] hi/lo bf16
__global__ void wprep_kernel(const float* __restrict__ src, int K, int N, int dstoff) {
    int i = blockIdx.x * blockDim.x + threadIdx.x;
    if (i >= K * N) return;
    int n = i / K, k = i % K;
    float v = src[(size_t)k * N + n];
    __nv_bfloat16 h = __float2bfloat16(v);
    g_Bhi[dstoff + i] = h;
    g_Blo[dstoff + i] = __float2bfloat16(v - __bfloat162float(h));
}

// split activations: src fp32 (n elems) -> g_Ahi/g_Alo
__global__ void aconv_kernel(const float* __restrict__ src, int n) {
    int i = blockIdx.x * blockDim.x + threadIdx.x;
    if (i >= n) return;
    float v = src[i];
    __nv_bfloat16 h = __float2bfloat16(v);
    g_Ahi[i] = h;
    g_Alo[i] = __float2bfloat16(v - __bfloat162float(h));
}

// =================== fused filter + edge message (atomic, R2-proven) ===================
__global__ void __launch_bounds__(128) edge_kernel(const float* __restrict__ W,
                                                   const float* __restrict__ b,
                                                   int layer,
                                                   const int* __restrict__ idx_i,
                                                   const int* __restrict__ idx_j,
                                                   const float* __restrict__ mu,
                                                   float* __restrict__ q) {
    int f = threadIdx.x;
    float w0[NRBF], w1[NRBF], w2[NRBF];
#pragma unroll
    for (int k = 0; k < NRBF; k++) {
        const float* row = W + k * (NL * 384) + layer * 384;
        w0[k] = row[f];
        w1[k] = row[128 + f];
        w2[k] = row[256 + f];
    }
    float b0 = b[layer * 384 + f];
    float b1v = b[layer * 384 + 128 + f];
    float b2v = b[layer * 384 + 256 + f];

    for (int e = blockIdx.x; e < NE; e += gridDim.x) {
        const float* p = g_phis + e * NRBF;
        float4 df = __ldg(g_dirf + e);
        float a0 = b0 * df.w, a1 = b1v * df.w, a2 = b2v * df.w;
#pragma unroll
        for (int k = 0; k < NRBF; k++) {
            float pk = __ldg(p + k);
            a0 += pk * w0[k];
            a1 += pk * w1[k];
            a2 += pk * w2[k];
        }
        int i = __ldg(idx_i + e), j = __ldg(idx_j + e);
        const float* xj = g_x + j * 384;
        float dq   = a0 * __ldg(xj + f);
        float dmuR = a1 * __ldg(xj + 128 + f);
        float dmm  = a2 * __ldg(xj + 256 + f);
        const float* mj = mu + j * 384;
        atomicAdd(q + i * 128 + f, dq);
        atomicAdd(g_dmu + i * 384 + f,       dmuR * df.x + dmm * __ldg(mj + f));
        atomicAdd(g_dmu + i * 384 + 128 + f, dmuR * df.y + dmm * __ldg(mj + 128 + f));
        atomicAdd(g_dmu + i * 384 + 256 + f, dmuR * df.z + dmm * __ldg(mj + 256 + f));
    }
}

__global__ void addmu_kernel(float* __restrict__ mu) {
    int i = blockIdx.x * blockDim.x + threadIdx.x;
    if (i >= NA * 384) return;
    mu[i] += g_dmu[i];
    g_dmu[i] = 0.0f;
}

// =================== mma.sync bf16x3 GEMM ===================
__device__ __forceinline__ void ldm_x4(uint32_t* r, uint32_t addr) {
    asm volatile("ldmatrix.sync.aligned.m8n8.x4.shared.b16 {%0,%1,%2,%3}, [%4];"
                 : "=r"(r[0]), "=r"(r[1]), "=r"(r[2]), "=r"(r[3]) : "r"(addr));
}
__device__ __forceinline__ void ldm_x2(uint32_t* r, uint32_t addr) {
    asm volatile("ldmatrix.sync.aligned.m8n8.x2.shared.b16 {%0,%1}, [%2];"
                 : "=r"(r[0]), "=r"(r[1]) : "r"(addr));
}
__device__ __forceinline__ void mma_bf16(float* d, const uint32_t* a, const uint32_t* b) {
    asm volatile(
        "mma.sync.aligned.m16n8k16.row.col.f32.bf16.bf16.f32 "
        "{%0,%1,%2,%3}, {%4,%5,%6,%7}, {%8,%9}, {%0,%1,%2,%3};"
        : "+f"(d[0]), "+f"(d[1]), "+f"(d[2]), "+f"(d[3])
        : "r"(a[0]), "r"(a[1]), "r"(a[2]), "r"(a[3]), "r"(b[0]), "r"(b[1]));
}
__device__ __forceinline__ uint32_t smem_u32(const void* p) {
    uint32_t a;
    asm("{ .reg .u64 t; cvta.to.shared.u64 t, %1; cvt.u32.u64 %0, t; }" : "=r"(a) : "l"(p));
    return a;
}

#define AS 40  // smem row stride (bf16 elems), 80B: 16B-aligned, conflict-light

// C(M,N) = act(A@Bt^T + bias); A split [M][K] bf16, Bt split [N][K] bf16.
// Block 128x128, 256 threads, 8 warps as 4(m) x 2(n); warp tile 32x64.
__global__ void __launch_bounds__(256) gemm_mma(const __nv_bfloat16* __restrict__ Ahi,
                                                const __nv_bfloat16* __restrict__ Alo,
                                                const __nv_bfloat16* __restrict__ Bhi,
                                                const __nv_bfloat16* __restrict__ Blo,
                                                const float* __restrict__ bias,
                                                float* __restrict__ C,
                                                int M, int N, int K, int act) {
    __shared__ __nv_bfloat16 sAh[128][AS], sAl[128][AS], sBh[128][AS], sBl[128][AS];
    int tid = threadIdx.x;
    int wid = tid >> 5, lane = tid & 31;
    int wm = wid & 3, wn = wid >> 2;
    int row0 = blockIdx.y * 128, col0 = blockIdx.x * 128;

    float acc[2][8][4];
#pragma unroll
    for (int i = 0; i < 2; i++)
#pragma unroll
        for (int j = 0; j < 8; j++)
#pragma unroll
            for (int k = 0; k < 4; k++) acc[i][j][k] = 0.f;

    // loaders: each thread moves 16 bf16 (2x uint4) per buffer per chunk
    int lrow = tid >> 1, lcol = (tid & 1) << 4;
    bool rowok = (row0 + lrow) < M;
    const __nv_bfloat16* pAh = Ahi + (size_t)(row0 + lrow) * K + lcol;
    const __nv_bfloat16* pAl = Alo + (size_t)(row0 + lrow) * K + lcol;
    const __nv_bfloat16* pBh = Bhi + (size_t)(col0 + lrow) * K + lcol;
    const __nv_bfloat16* pBl = Blo + (size_t)(col0 + lrow) * K + lcol;
    const uint4 z4 = make_uint4(0, 0, 0, 0);

    // ldmatrix addresses
    uint32_t aAh = smem_u32(&sAh[wm * 32][0]);
    uint32_t aAl = smem_u32(&sAl[wm * 32][0]);
    uint32_t aBh = smem_u32(&sBh[wn * 64][0]);
    uint32_t aBl = smem_u32(&sBl[wn * 64][0]);

    for (int c = 0; c < (K >> 5); c++) {
#pragma unroll
        for (int u = 0; u < 2; u++) {
            int co = c * 32 + u * 8;
            *(uint4*)&sAh[lrow][lcol + u * 8] = rowok ? *(const uint4*)(pAh + co) : z4;
            *(uint4*)&sAl[lrow][lcol + u * 8] = rowok ? *(const uint4*)(pAl + co) : z4;
            *(uint4*)&sBh[lrow][lcol + u * 8] = *(const uint4*)(pBh + co);
            *(uint4*)&sBl[lrow][lcol + u * 8] = *(const uint4*)(pBl + co);
        }
        __syncthreads();
#pragma unroll
        for (int ks = 0; ks < 2; ks++) {
            int kk = ks * 16;
            uint32_t ah[2][4], al[2][4];
            // A frag: rows mt*16 + lane%16, col kk + (lane/16)*8
            uint32_t aoff = ((lane & 15) * AS + kk + ((lane >> 4) << 3)) * 2;
#pragma unroll
            for (int mt = 0; mt < 2; mt++) {
                ldm_x4(ah[mt], aAh + mt * 16 * AS * 2 + aoff);
                ldm_x4(al[mt], aAl + mt * 16 * AS * 2 + aoff);
            }
            // B frag: rows nt*8 + lane%8, col kk + ((lane>>3)&1)*8
            uint32_t boff = ((lane & 7) * AS + kk + (((lane >> 3) & 1) << 3)) * 2;
#pragma unroll
            for (int nt = 0; nt < 8; nt++) {
                uint32_t bh[2], bl[2];
                ldm_x2(bh, aBh + nt * 8 * AS * 2 + boff);
                ldm_x2(bl, aBl + nt * 8 * AS * 2 + boff);
#pragma unroll
                for (int mt = 0; mt < 2; mt++) {
                    mma_bf16(acc[mt][nt], ah[mt], bh);
                    mma_bf16(acc[mt][nt], ah[mt], bl);
                    mma_bf16(acc[mt][nt], al[mt], bh);
                }
            }
        }
        __syncthreads();
    }

    // epilogue: bias + optional silu, direct coalesced-ish float2 stores
    int gid = lane >> 2, tig = lane & 3;
#pragma unroll
    for (int mt = 0; mt < 2; mt++) {
#pragma unroll
        for (int nt = 0; nt < 8; nt++) {
            int cc = col0 + wn * 64 + nt * 8 + tig * 2;
            float b0 = __ldg(bias + cc), b1 = __ldg(bias + cc + 1);
            int r0 = row0 + wm * 32 + mt * 16 + gid;
            float v0 = acc[mt][nt][0] + b0, v1 = acc[mt][nt][1] + b1;
            float v2 = acc[mt][nt][2] + b0, v3 = acc[mt][nt][3] + b1;
            if (act) {
                v0 = v0 / (1.0f + expf(-v0));
                v1 = v1 / (1.0f + expf(-v1));
                v2 = v2 / (1.0f + expf(-v2));
                v3 = v3 / (1.0f + expf(-v3));
            }
            if (r0 < M) *(float2*)(C + (size_t)r0 * N + cc) = make_float2(v0, v1);
            if (r0 + 8 < M) *(float2*)(C + (size_t)(r0 + 8) * N + cc) = make_float2(v2, v3);
        }
    }
}

// =================== ctx / update ===================
__global__ void ctx_kernel(const float* __restrict__ q) {
    int i = blockIdx.x * blockDim.x + threadIdx.x;
    if (i >= NA * FF) return;
    int a = i >> 7, f = i & 127;
    float v0 = g_mumix[(a * 3 + 0) * 256 + f];
    float v1 = g_mumix[(a * 3 + 1) * 256 + f];
    float v2 = g_mumix[(a * 3 + 2) * 256 + f];
    g_ctx[a * 256 + f] = q[i];
    g_ctx[a * 256 + 128 + f] = sqrtf(v0 * v0 + v1 * v1 + v2 * v2);
}

__global__ void update_kernel(float* __restrict__ q, float* __restrict__ mu) {
    int i = blockIdx.x * blockDim.x + threadIdx.x;
    if (i >= NA * FF) return;
    int a = i >> 7, f = i & 127;
    float s = 0.0f;
    float xmu = g_x[a * 384 + 128 + f];
#pragma unroll
    for (int d = 0; d < 3; d++) {
        float mv = g_mumix[(a * 3 + d) * 256 + f];
        float mw = g_mumix[(a * 3 + d) * 256 + 128 + f];
        s += mv * mw;
        mu[a * 384 + d * 128 + f] += xmu * mw;
    }
    q[i] += g_x[a * 384 + f] + g_x[a * 384 + 256 + f] * s;
}

// =================== launcher ===================
extern "C" void kernel_launch(void* const* d_in, const int* in_sizes, int n_in,
                              void* d_out, int out_size) {
    const float* r_ij      = (const float*)d_in[0];
    const float* embedding = (const float*)d_in[1];
    const float* filt_W    = (const float*)d_in[2];
    const float* filt_b    = (const float*)d_in[3];
    const float* inter_W1  = (const float*)d_in[4];
    const float* inter_b1  = (const float*)d_in[5];
    const float* inter_W2  = (const float*)d_in[6];
    const float* inter_b2  = (const float*)d_in[7];
    const float* mix_W     = (const float*)d_in[8];
    const float* mix_b     = (const float*)d_in[9];
    const float* intra_W1  = (const float*)d_in[10];
    const float* intra_b1  = (const float*)d_in[11];
    const float* intra_W2  = (const float*)d_in[12];
    const float* intra_b2  = (const float*)d_in[13];
    const int*   z         = (const int*)d_in[14];
    const int*   idx_i     = (const int*)d_in[15];
    const int*   idx_j     = (const int*)d_in[16];

    float* q  = (float*)d_out;
    float* mu = q + (size_t)NA * FF;  // [NA][3][128] => a*384 + d*128 + f

    void *p_h, *p_x, *p_ctx, *p_mumix, *p_Ahi, *p_Alo, *p_Bhi, *p_Blo;
    cudaGetSymbolAddress(&p_h, g_h);
    cudaGetSymbolAddress(&p_x, g_x);
    cudaGetSymbolAddress(&p_ctx, g_ctx);
    cudaGetSymbolAddress(&p_mumix, g_mumix);
    cudaGetSymbolAddress(&p_Ahi, g_Ahi);
    cudaGetSymbolAddress(&p_Alo, g_Alo);
    cudaGetSymbolAddress(&p_Bhi, g_Bhi);
    cudaGetSymbolAddress(&p_Blo, g_Blo);
    float* hbuf  = (float*)p_h;
    float* xbuf  = (float*)p_x;
    float* ctx   = (float*)p_ctx;
    float* mumix = (float*)p_mumix;
    __nv_bfloat16* Ahi = (__nv_bfloat16*)p_Ahi;
    __nv_bfloat16* Alo = (__nv_bfloat16*)p_Alo;
    __nv_bfloat16* Bhi = (__nv_bfloat16*)p_Bhi;
    __nv_bfloat16* Blo = (__nv_bfloat16*)p_Blo;

    geom_kernel<<<(NE + 255) / 256, 256>>>(r_ij);
    init_kernel<<<(NA * 384 + 255) / 256, 256>>>(z, embedding, q, mu);

    // weight prep: transpose+split each layer's weights
    for (int l = 0; l < NL; l++) {
        int base = l * WL;
        wprep_kernel<<<(128 * 128 + 255) / 256, 256>>>(inter_W1 + (size_t)l * 128 * 128, 128, 128, base + 0);
        wprep_kernel<<<(128 * 384 + 255) / 256, 256>>>(inter_W2 + (size_t)l * 128 * 384, 128, 384, base + 16384);
        wprep_kernel<<<(128 * 256 + 255) / 256, 256>>>(mix_W + (size_t)l * 128 * 256, 128, 256, base + 65536);
        wprep_kernel<<<(256 * 128 + 255) / 256, 256>>>(intra_W1 + (size_t)l * 256 * 128, 256, 128, base + 98304);
        wprep_kernel<<<(128 * 384 + 255) / 256, 256>>>(intra_W2 + (size_t)l * 128 * 384, 128, 384, base + 131072);
    }

    for (int l = 0; l < NL; l++) {
        int wb = l * WL;
        // h = silu(q @ W1 + b1)
        aconv_kernel<<<(NA * 128 + 255) / 256, 256>>>(q, NA * 128);
        gemm_mma<<<dim3(1, (NA + 127) / 128), 256>>>(
            Ahi, Alo, Bhi + wb, Blo + wb, inter_b1 + l * 128, hbuf, NA, 128, 128, 1);
        // x = h @ W2 + b2
        aconv_kernel<<<(NA * 128 + 255) / 256, 256>>>(hbuf, NA * 128);
        gemm_mma<<<dim3(3, (NA + 127) / 128), 256>>>(
            Ahi, Alo, Bhi + wb + 16384, Blo + wb + 16384, inter_b2 + l * 384, xbuf, NA, 384, 128, 0);
        // fused filters + edge messages (atomics into q, g_dmu)
        edge_kernel<<<2368, 128>>>(filt_W, filt_b, l, idx_i, idx_j, mu, q);
        addmu_kernel<<<(NA * 384 + 255) / 256, 256>>>(mu);
        // mu_mix = mu @ mix_W + mix_b   (45000 x 256)
        aconv_kernel<<<(NA * 384 + 255) / 256, 256>>>(mu, NA * 384);
        gemm_mma<<<dim3(2, (NA * 3 + 127) / 128), 256>>>(
            Ahi, Alo, Bhi + wb + 65536, Blo + wb + 65536, mix_b + l * 256, mumix, NA * 3, 256, 128, 0);
        // ctx = [q, ||mu_V||]
        ctx_kernel<<<(NA * FF + 255) / 256, 256>>>(q);
        // h = silu(ctx @ intra_W1 + b1)  (K=256)
        aconv_kernel<<<(NA * 256 + 255) / 256, 256>>>(ctx, NA * 256);
        gemm_mma<<<dim3(1, (NA + 127) / 128), 256>>>(
            Ahi, Alo, Bhi + wb + 98304, Blo + wb + 98304, intra_b1 + l * 128, hbuf, NA, 128, 256, 1);
        // x = h @ intra_W2 + b2
        aconv_kernel<<<(NA * 128 + 255) / 256, 256>>>(hbuf, NA * 128);
        gemm_mma<<<dim3(3, (NA + 127) / 128), 256>>>(
            Ahi, Alo, Bhi + wb + 131072, Blo + wb + 131072, intra_b2 + l * 384, xbuf, NA, 384, 128, 0);
        // q += dq_intra + dqmu_intra ; mu += dmu_intra
        update_kernel<<<(NA * FF + 255) / 256, 256>>>(q, mu);
    }
}

// round 7
// speedup vs baseline: 1.3034x; 1.0789x over previous
#include <cuda_runtime.h>
#include <cuda_bf16.h>
#include <math.h>
#include <stdint.h>

#define NA 15000
#define NE 300000
#define FF 128
#define NRBF 20
#define NL 3
#define CUTOFF 5.0f
#define PI_F 3.14159265358979f

// =================== static scratch ===================
__device__ float4 g_dirf[NE];         // (dir.xyz, fcut)
__device__ float g_phis[NE * NRBF];   // phi * fcut
__device__ float g_x[NA * 384];
__device__ float g_mumix[NA * 3 * 256];
__device__ float g_dmu[NA * 384];
// bf16 hi/lo split operands
__device__ __nv_bfloat16 g_qhi[NA * 128], g_qlo[NA * 128];
__device__ __nv_bfloat16 g_hhi[NA * 128], g_hlo[NA * 128];
__device__ __nv_bfloat16 g_muhi[NA * 384], g_mulo[NA * 384];
__device__ __nv_bfloat16 g_chi[NA * 256], g_clo[NA * 256];
#define WL 180224  // per-layer transposed-weight elems
__device__ __nv_bfloat16 g_Bhi[NL * WL];
__device__ __nv_bfloat16 g_Blo[NL * WL];
// offsets inside a WL block: w1t 0, w2t 16384, mixt 65536, iw1t 98304, iw2t 131072

__device__ __forceinline__ void split_store(__nv_bfloat16* hi, __nv_bfloat16* lo,
                                            size_t off, float v0, float v1) {
    __nv_bfloat16 h0 = __float2bfloat16(v0), h1 = __float2bfloat16(v1);
    __nv_bfloat162 H, L;
    H.x = h0; H.y = h1;
    L.x = __float2bfloat16(v0 - __bfloat162float(h0));
    L.y = __float2bfloat16(v1 - __bfloat162float(h1));
    *(__nv_bfloat162*)(hi + off) = H;
    *(__nv_bfloat162*)(lo + off) = L;
}

// =================== small kernels ===================
__global__ void geom_kernel(const float* __restrict__ rij) {
    int e = blockIdx.x * blockDim.x + threadIdx.x;
    if (e >= NE) return;
    float r0 = rij[e * 3 + 0], r1 = rij[e * 3 + 1], r2 = rij[e * 3 + 2];
    float d = sqrtf(r0 * r0 + r1 * r1 + r2 * r2);
    float inv = 1.0f / d;
    float fc = (d < CUTOFF) ? 0.5f * (cosf(d * PI_F / CUTOFF) + 1.0f) : 0.0f;
    g_dirf[e] = make_float4(r0 * inv, r1 * inv, r2 * inv, fc);
    const float width = CUTOFF / (NRBF - 1);
    const float coeff = -0.5f / (width * width);
#pragma unroll
    for (int k = 0; k < NRBF; k++) {
        float t = d - width * k;
        g_phis[e * NRBF + k] = expf(coeff * t * t) * fc;
    }
}

__global__ void init_kernel(const int* __restrict__ z, const float* __restrict__ emb,
                            float* __restrict__ q, float* __restrict__ mu) {
    int i = blockIdx.x * blockDim.x + threadIdx.x;
    if (i >= NA * 384) return;
    mu[i] = 0.0f;
    g_dmu[i] = 0.0f;
    if (i < NA * FF) {
        int a = i >> 7, f = i & 127;
        float v = emb[z[a] * FF + f];
        q[i] = v;
        __nv_bfloat16 h = __float2bfloat16(v);
        g_qhi[i] = h;
        g_qlo[i] = __float2bfloat16(v - __bfloat162float(h));
    }
}

// transpose+split weights for ALL layers: src (NL,K,N) fp32 -> g_B*[l*WL+dstoff + n*K+k]
__global__ void wprep_kernel(const float* __restrict__ src, int K, int N, int dstoff) {
    int i = blockIdx.x * blockDim.x + threadIdx.x;
    if (i >= NL * K * N) return;
    int l = i / (K * N), r = i % (K * N);
    int n = r / K, k = r % K;
    float v = src[(size_t)l * K * N + (size_t)k * N + n];
    __nv_bfloat16 h = __float2bfloat16(v);
    g_Bhi[l * WL + dstoff + r] = h;
    g_Blo[l * WL + dstoff + r] = __float2bfloat16(v - __bfloat162float(h));
}

// =================== fused filter + edge message (atomic; float4 phi) ===================
__global__ void __launch_bounds__(128) edge_kernel(const float* __restrict__ W,
                                                   const float* __restrict__ b,
                                                   int layer,
                                                   const int* __restrict__ idx_i,
                                                   const int* __restrict__ idx_j,
                                                   const float* __restrict__ mu,
                                                   float* __restrict__ q) {
    int f = threadIdx.x;
    float w0[NRBF], w1[NRBF], w2[NRBF];
#pragma unroll
    for (int k = 0; k < NRBF; k++) {
        const float* row = W + k * (NL * 384) + layer * 384;
        w0[k] = row[f];
        w1[k] = row[128 + f];
        w2[k] = row[256 + f];
    }
    float b0 = b[layer * 384 + f];
    float b1v = b[layer * 384 + 128 + f];
    float b2v = b[layer * 384 + 256 + f];

    for (int e = blockIdx.x; e < NE; e += gridDim.x) {
        const float4* p4 = (const float4*)(g_phis + e * NRBF);
        float4 P0 = __ldg(p4 + 0), P1 = __ldg(p4 + 1), P2 = __ldg(p4 + 2),
               P3 = __ldg(p4 + 3), P4 = __ldg(p4 + 4);
        float ph[NRBF] = {P0.x, P0.y, P0.z, P0.w, P1.x, P1.y, P1.z, P1.w,
                          P2.x, P2.y, P2.z, P2.w, P3.x, P3.y, P3.z, P3.w,
                          P4.x, P4.y, P4.z, P4.w};
        float4 df = __ldg(g_dirf + e);
        float a0 = b0 * df.w, a1 = b1v * df.w, a2 = b2v * df.w;
#pragma unroll
        for (int k = 0; k < NRBF; k++) {
            a0 += ph[k] * w0[k];
            a1 += ph[k] * w1[k];
            a2 += ph[k] * w2[k];
        }
        int i = __ldg(idx_i + e), j = __ldg(idx_j + e);
        const float* xj = g_x + j * 384;
        float dq   = a0 * __ldg(xj + f);
        float dmuR = a1 * __ldg(xj + 128 + f);
        float dmm  = a2 * __ldg(xj + 256 + f);
        const float* mj = mu + j * 384;
        atomicAdd(q + i * 128 + f, dq);
        atomicAdd(g_dmu + i * 384 + f,       dmuR * df.x + dmm * __ldg(mj + f));
        atomicAdd(g_dmu + i * 384 + 128 + f, dmuR * df.y + dmm * __ldg(mj + 128 + f));
        atomicAdd(g_dmu + i * 384 + 256 + f, dmuR * df.z + dmm * __ldg(mj + 256 + f));
    }
}

// mu += dmu; dmu = 0; emit mu hi/lo split
__global__ void addmu_kernel(float* __restrict__ mu) {
    int i = (blockIdx.x * blockDim.x + threadIdx.x) * 2;
    if (i >= NA * 384) return;
    float v0 = mu[i] + g_dmu[i];
    float v1 = mu[i + 1] + g_dmu[i + 1];
    mu[i] = v0;
    mu[i + 1] = v1;
    g_dmu[i] = 0.0f;
    g_dmu[i + 1] = 0.0f;
    split_store(g_muhi, g_mulo, i, v0, v1);
}

// =================== mma.sync bf16x3 GEMM ===================
__device__ __forceinline__ void ldm_x4(uint32_t* r, uint32_t addr) {
    asm volatile("ldmatrix.sync.aligned.m8n8.x4.shared.b16 {%0,%1,%2,%3}, [%4];"
                 : "=r"(r[0]), "=r"(r[1]), "=r"(r[2]), "=r"(r[3]) : "r"(addr));
}
__device__ __forceinline__ void ldm_x2(uint32_t* r, uint32_t addr) {
    asm volatile("ldmatrix.sync.aligned.m8n8.x2.shared.b16 {%0,%1}, [%2];"
                 : "=r"(r[0]), "=r"(r[1]) : "r"(addr));
}
__device__ __forceinline__ void mma_bf16(float* d, const uint32_t* a, const uint32_t* b) {
    asm volatile(
        "mma.sync.aligned.m16n8k16.row.col.f32.bf16.bf16.f32 "
        "{%0,%1,%2,%3}, {%4,%5,%6,%7}, {%8,%9}, {%0,%1,%2,%3};"
        : "+f"(d[0]), "+f"(d[1]), "+f"(d[2]), "+f"(d[3])
        : "r"(a[0]), "r"(a[1]), "r"(a[2]), "r"(a[3]), "r"(b[0]), "r"(b[1]));
}
__device__ __forceinline__ uint32_t smem_u32(const void* p) {
    uint32_t a;
    asm("{ .reg .u64 t; cvta.to.shared.u64 t, %1; cvt.u32.u64 %0, t; }" : "=r"(a) : "l"(p));
    return a;
}

#define AS 40  // smem row stride (bf16 elems)

// C(M,N) = act(A@Bt^T + bias). Optional fp32 C and/or bf16 hi/lo split outputs.
__global__ void __launch_bounds__(256) gemm_mma(const __nv_bfloat16* __restrict__ Ahi,
                                                const __nv_bfloat16* __restrict__ Alo,
                                                const __nv_bfloat16* __restrict__ Bhi,
                                                const __nv_bfloat16* __restrict__ Blo,
                                                const float* __restrict__ bias,
                                                float* __restrict__ C,
                                                __nv_bfloat16* __restrict__ Shi,
                                                __nv_bfloat16* __restrict__ Slo,
                                                int M, int N, int K, int act) {
    __shared__ __nv_bfloat16 sAh[128][AS], sAl[128][AS], sBh[128][AS], sBl[128][AS];
    int tid = threadIdx.x;
    int wid = tid >> 5, lane = tid & 31;
    int wm = wid & 3, wn = wid >> 2;
    int row0 = blockIdx.y * 128, col0 = blockIdx.x * 128;

    float acc[2][8][4];
#pragma unroll
    for (int i = 0; i < 2; i++)
#pragma unroll
        for (int j = 0; j < 8; j++)
#pragma unroll
            for (int k = 0; k < 4; k++) acc[i][j][k] = 0.f;

    int lrow = tid >> 1, lcol = (tid & 1) << 4;
    bool rowok = (row0 + lrow) < M;
    const __nv_bfloat16* pAh = Ahi + (size_t)(row0 + lrow) * K + lcol;
    const __nv_bfloat16* pAl = Alo + (size_t)(row0 + lrow) * K + lcol;
    const __nv_bfloat16* pBh = Bhi + (size_t)(col0 + lrow) * K + lcol;
    const __nv_bfloat16* pBl = Blo + (size_t)(col0 + lrow) * K + lcol;
    const uint4 z4 = make_uint4(0, 0, 0, 0);

    uint32_t aAh = smem_u32(&sAh[wm * 32][0]);
    uint32_t aAl = smem_u32(&sAl[wm * 32][0]);
    uint32_t aBh = smem_u32(&sBh[wn * 64][0]);
    uint32_t aBl = smem_u32(&sBl[wn * 64][0]);

    for (int c = 0; c < (K >> 5); c++) {
#pragma unroll
        for (int u = 0; u < 2; u++) {
            int co = c * 32 + u * 8;
            *(uint4*)&sAh[lrow][lcol + u * 8] = rowok ? *(const uint4*)(pAh + co) : z4;
            *(uint4*)&sAl[lrow][lcol + u * 8] = rowok ? *(const uint4*)(pAl + co) : z4;
            *(uint4*)&sBh[lrow][lcol + u * 8] = *(const uint4*)(pBh + co);
            *(uint4*)&sBl[lrow][lcol + u * 8] = *(const uint4*)(pBl + co);
        }
        __syncthreads();
#pragma unroll
        for (int ks = 0; ks < 2; ks++) {
            int kk = ks * 16;
            uint32_t ah[2][4], al[2][4];
            uint32_t aoff = ((lane & 15) * AS + kk + ((lane >> 4) << 3)) * 2;
#pragma unroll
            for (int mt = 0; mt < 2; mt++) {
                ldm_x4(ah[mt], aAh + mt * 16 * AS * 2 + aoff);
                ldm_x4(al[mt], aAl + mt * 16 * AS * 2 + aoff);
            }
            uint32_t boff = ((lane & 7) * AS + kk + (((lane >> 3) & 1) << 3)) * 2;
#pragma unroll
            for (int nt = 0; nt < 8; nt++) {
                uint32_t bh[2], bl[2];
                ldm_x2(bh, aBh + nt * 8 * AS * 2 + boff);
                ldm_x2(bl, aBl + nt * 8 * AS * 2 + boff);
#pragma unroll
                for (int mt = 0; mt < 2; mt++) {
                    mma_bf16(acc[mt][nt], ah[mt], bh);
                    mma_bf16(acc[mt][nt], ah[mt], bl);
                    mma_bf16(acc[mt][nt], al[mt], bh);
                }
            }
        }
        __syncthreads();
    }

    int gid = lane >> 2, tig = lane & 3;
#pragma unroll
    for (int mt = 0; mt < 2; mt++) {
#pragma unroll
        for (int nt = 0; nt < 8; nt++) {
            int cc = col0 + wn * 64 + nt * 8 + tig * 2;
            float b0 = __ldg(bias + cc), b1 = __ldg(bias + cc + 1);
            int r0 = row0 + wm * 32 + mt * 16 + gid;
            float v0 = acc[mt][nt][0] + b0, v1 = acc[mt][nt][1] + b1;
            float v2 = acc[mt][nt][2] + b0, v3 = acc[mt][nt][3] + b1;
            if (act) {
                v0 = v0 / (1.0f + expf(-v0));
                v1 = v1 / (1.0f + expf(-v1));
                v2 = v2 / (1.0f + expf(-v2));
                v3 = v3 / (1.0f + expf(-v3));
            }
            if (r0 < M) {
                size_t o = (size_t)r0 * N + cc;
                if (C) *(float2*)(C + o) = make_float2(v0, v1);
                if (Shi) split_store(Shi, Slo, o, v0, v1);
            }
            if (r0 + 8 < M) {
                size_t o = (size_t)(r0 + 8) * N + cc;
                if (C) *(float2*)(C + o) = make_float2(v2, v3);
                if (Shi) split_store(Shi, Slo, o, v2, v3);
            }
        }
    }
}

// =================== ctx / update ===================
// ctx = [q, ||mu_V||] -> bf16 hi/lo split only
__global__ void ctx_kernel(const float* __restrict__ q) {
    int i = (blockIdx.x * blockDim.x + threadIdx.x) * 2;
    if (i >= NA * FF) return;
    int a = i >> 7, f = i & 127;
    float n0, n1;
    {
        float v0 = g_mumix[(a * 3 + 0) * 256 + f];
        float v1 = g_mumix[(a * 3 + 1) * 256 + f];
        float v2 = g_mumix[(a * 3 + 2) * 256 + f];
        n0 = sqrtf(v0 * v0 + v1 * v1 + v2 * v2);
        float u0 = g_mumix[(a * 3 + 0) * 256 + f + 1];
        float u1 = g_mumix[(a * 3 + 1) * 256 + f + 1];
        float u2 = g_mumix[(a * 3 + 2) * 256 + f + 1];
        n1 = sqrtf(u0 * u0 + u1 * u1 + u2 * u2);
    }
    split_store(g_chi, g_clo, (size_t)a * 256 + f, q[i], q[i + 1]);
    split_store(g_chi, g_clo, (size_t)a * 256 + 128 + f, n0, n1);
}

// q += dq_intra + dqmu_intra (emit q split); mu += dmu_intra
__global__ void update_kernel(float* __restrict__ q, float* __restrict__ mu) {
    int i = (blockIdx.x * blockDim.x + threadIdx.x) * 2;
    if (i >= NA * FF) return;
    int a = i >> 7, f = i & 127;
    float s0 = 0.0f, s1 = 0.0f;
    float xmu0 = g_x[a * 384 + 128 + f], xmu1 = g_x[a * 384 + 128 + f + 1];
#pragma unroll
    for (int d = 0; d < 3; d++) {
        float mv0 = g_mumix[(a * 3 + d) * 256 + f];
        float mw0 = g_mumix[(a * 3 + d) * 256 + 128 + f];
        float mv1 = g_mumix[(a * 3 + d) * 256 + f + 1];
        float mw1 = g_mumix[(a * 3 + d) * 256 + 128 + f + 1];
        s0 += mv0 * mw0;
        s1 += mv1 * mw1;
        mu[a * 384 + d * 128 + f] += xmu0 * mw0;
        mu[a * 384 + d * 128 + f + 1] += xmu1 * mw1;
    }
    float q0 = q[i] + g_x[a * 384 + f] + g_x[a * 384 + 256 + f] * s0;
    float q1 = q[i + 1] + g_x[a * 384 + f + 1] + g_x[a * 384 + 256 + f + 1] * s1;
    q[i] = q0;
    q[i + 1] = q1;
    split_store(g_qhi, g_qlo, i, q0, q1);
}

// =================== launcher ===================
extern "C" void kernel_launch(void* const* d_in, const int* in_sizes, int n_in,
                              void* d_out, int out_size) {
    const float* r_ij      = (const float*)d_in[0];
    const float* embedding = (const float*)d_in[1];
    const float* filt_W    = (const float*)d_in[2];
    const float* filt_b    = (const float*)d_in[3];
    const float* inter_W1  = (const float*)d_in[4];
    const float* inter_b1  = (const float*)d_in[5];
    const float* inter_W2  = (const float*)d_in[6];
    const float* inter_b2  = (const float*)d_in[7];
    const float* mix_W     = (const float*)d_in[8];
    const float* mix_b     = (const float*)d_in[9];
    const float* intra_W1  = (const float*)d_in[10];
    const float* intra_b1  = (const float*)d_in[11];
    const float* intra_W2  = (const float*)d_in[12];
    const float* intra_b2  = (const float*)d_in[13];
    const int*   z         = (const int*)d_in[14];
    const int*   idx_i     = (const int*)d_in[15];
    const int*   idx_j     = (const int*)d_in[16];

    float* q  = (float*)d_out;
    float* mu = q + (size_t)NA * FF;  // [NA][3][128]

    void *p_x, *p_mumix, *p_qhi, *p_qlo, *p_hhi, *p_hlo, *p_muhi, *p_mulo, *p_chi, *p_clo,
        *p_Bhi, *p_Blo;
    cudaGetSymbolAddress(&p_x, g_x);
    cudaGetSymbolAddress(&p_mumix, g_mumix);
    cudaGetSymbolAddress(&p_qhi, g_qhi);
    cudaGetSymbolAddress(&p_qlo, g_qlo);
    cudaGetSymbolAddress(&p_hhi, g_hhi);
    cudaGetSymbolAddress(&p_hlo, g_hlo);
    cudaGetSymbolAddress(&p_muhi, g_muhi);
    cudaGetSymbolAddress(&p_mulo, g_mulo);
    cudaGetSymbolAddress(&p_chi, g_chi);
    cudaGetSymbolAddress(&p_clo, g_clo);
    cudaGetSymbolAddress(&p_Bhi, g_Bhi);
    cudaGetSymbolAddress(&p_Blo, g_Blo);
    float* xbuf  = (float*)p_x;
    float* mumix = (float*)p_mumix;
    __nv_bfloat16 *qhi = (__nv_bfloat16*)p_qhi, *qlo = (__nv_bfloat16*)p_qlo;
    __nv_bfloat16 *hhi = (__nv_bfloat16*)p_hhi, *hlo = (__nv_bfloat16*)p_hlo;
    __nv_bfloat16 *muhi = (__nv_bfloat16*)p_muhi, *mulo = (__nv_bfloat16*)p_mulo;
    __nv_bfloat16 *chi = (__nv_bfloat16*)p_chi, *clo = (__nv_bfloat16*)p_clo;
    __nv_bfloat16 *Bhi = (__nv_bfloat16*)p_Bhi, *Blo = (__nv_bfloat16*)p_Blo;

    geom_kernel<<<(NE + 255) / 256, 256>>>(r_ij);
    init_kernel<<<(NA * 384 + 255) / 256, 256>>>(z, embedding, q, mu);

    // weight prep (all layers per launch)
    wprep_kernel<<<(NL * 128 * 128 + 255) / 256, 256>>>(inter_W1, 128, 128, 0);
    wprep_kernel<<<(NL * 128 * 384 + 255) / 256, 256>>>(inter_W2, 128, 384, 16384);
    wprep_kernel<<<(NL * 128 * 256 + 255) / 256, 256>>>(mix_W, 128, 256, 65536);
    wprep_kernel<<<(NL * 256 * 128 + 255) / 256, 256>>>(intra_W1, 256, 128, 98304);
    wprep_kernel<<<(NL * 128 * 384 + 255) / 256, 256>>>(intra_W2, 128, 384, 131072);

    for (int l = 0; l < NL; l++) {
        int wb = l * WL;
        // h = silu(q @ W1 + b1) -> split only
        gemm_mma<<<dim3(1, (NA + 127) / 128), 256>>>(
            qhi, qlo, Bhi + wb, Blo + wb, inter_b1 + l * 128,
            nullptr, hhi, hlo, NA, 128, 128, 1);
        // x = h @ W2 + b2 -> fp32
        gemm_mma<<<dim3(3, (NA + 127) / 128), 256>>>(
            hhi, hlo, Bhi + wb + 16384, Blo + wb + 16384, inter_b2 + l * 384,
            xbuf, nullptr, nullptr, NA, 384, 128, 0);
        // fused filters + edge messages (atomics into q, g_dmu)
        edge_kernel<<<2368, 128>>>(filt_W, filt_b, l, idx_i, idx_j, mu, q);
        // mu += dmu (emit mu split)
        addmu_kernel<<<(NA * 192 + 255) / 256, 256>>>(mu);
        // mu_mix = mu @ mix_W + mix_b -> fp32
        gemm_mma<<<dim3(2, (NA * 3 + 127) / 128), 256>>>(
            muhi, mulo, Bhi + wb + 65536, Blo + wb + 65536, mix_b + l * 256,
            mumix, nullptr, nullptr, NA * 3, 256, 128, 0);
        // ctx = [q, ||mu_V||] -> split only
        ctx_kernel<<<(NA * 64 + 255) / 256, 256>>>(q);
        // h = silu(ctx @ intra_W1 + b1) -> split only
        gemm_mma<<<dim3(1, (NA + 127) / 128), 256>>>(
            chi, clo, Bhi + wb + 98304, Blo + wb + 98304, intra_b1 + l * 128,
            nullptr, hhi, hlo, NA, 128, 256, 1);
        // x = h @ intra_W2 + b2 -> fp32
        gemm_mma<<<dim3(3, (NA + 127) / 128), 256>>>(
            hhi, hlo, Bhi + wb + 131072, Blo + wb + 131072, intra_b2 + l * 384,
            xbuf, nullptr, nullptr, NA, 384, 128, 0);
        // q += dq_intra + dqmu_intra (emit q split); mu += dmu_intra
        update_kernel<<<(NA * 64 + 255) / 256, 256>>>(q, mu);
    }
}

// round 8
// speedup vs baseline: 1.3490x; 1.0349x over previous
#include <cuda_runtime.h>
#include <cuda_bf16.h>
#include <math.h>
#include <stdint.h>
#include <limits.h>

#define NA 15000
#define NE 300000
#define FF 128
#define NRBF 20
#define NL 3
#define CUTOFF 5.0f
#define PI_F 3.14159265358979f

// =================== static scratch ===================
__device__ float4 g_dirfS[NE];          // sorted: (dir.xyz, fcut)
__device__ __nv_bfloat16 g_phh[(size_t)NE * 32];  // sorted, padded phi hi (k20=fcut, 21..31=0)
__device__ __nv_bfloat16 g_phl[(size_t)NE * 32];  // sorted phi lo
__device__ int g_is[NE], g_js[NE], g_perm[NE];
__device__ int g_cnt[NA], g_head[NA];
__device__ float g_x[NA * 384];
__device__ float g_mumix[NA * 3 * 256];
__device__ float g_dmu[NA * 384];
// bf16 hi/lo split operands
__device__ __nv_bfloat16 g_qhi[NA * 128], g_qlo[NA * 128];
__device__ __nv_bfloat16 g_hhi[NA * 128], g_hlo[NA * 128];
__device__ __nv_bfloat16 g_muhi[NA * 384], g_mulo[NA * 384];
__device__ __nv_bfloat16 g_chi[NA * 256], g_clo[NA * 256];
#define WL 180224
__device__ __nv_bfloat16 g_Bhi[NL * WL];
__device__ __nv_bfloat16 g_Blo[NL * WL];
// filter weights transposed+padded: [l][n=384][k=32]
__device__ __nv_bfloat16 g_FWh[NL * 384 * 32];
__device__ __nv_bfloat16 g_FWl[NL * 384 * 32];

__device__ __forceinline__ void split_store(__nv_bfloat16* hi, __nv_bfloat16* lo,
                                            size_t off, float v0, float v1) {
    __nv_bfloat16 h0 = __float2bfloat16(v0), h1 = __float2bfloat16(v1);
    __nv_bfloat162 H, L;
    H.x = h0; H.y = h1;
    L.x = __float2bfloat16(v0 - __bfloat162float(h0));
    L.y = __float2bfloat16(v1 - __bfloat162float(h1));
    *(__nv_bfloat162*)(hi + off) = H;
    *(__nv_bfloat162*)(lo + off) = L;
}

// =================== CSR build ===================
__global__ void init_kernel(const int* __restrict__ z, const float* __restrict__ emb,
                            float* __restrict__ q, float* __restrict__ mu) {
    int i = blockIdx.x * blockDim.x + threadIdx.x;
    if (i >= NA * 384) return;
    mu[i] = 0.0f;
    g_dmu[i] = 0.0f;
    if (i < NA) g_cnt[i] = 0;
    if (i < NA * FF) {
        int a = i >> 7, f = i & 127;
        float v = emb[z[a] * FF + f];
        q[i] = v;
        __nv_bfloat16 h = __float2bfloat16(v);
        g_qhi[i] = h;
        g_qlo[i] = __float2bfloat16(v - __bfloat162float(h));
    }
}

__global__ void hist_kernel(const int* __restrict__ idx_i) {
    int e = blockIdx.x * blockDim.x + threadIdx.x;
    if (e < NE) atomicAdd(&g_cnt[idx_i[e]], 1);
}

#define SCAN_T 1024
#define SCAN_CH ((NA + SCAN_T - 1) / SCAN_T)
__global__ void __launch_bounds__(SCAN_T) scan_kernel() {
    __shared__ int sh[SCAN_T];
    int t = threadIdx.x;
    int start = t * SCAN_CH;
    int s = 0;
#pragma unroll
    for (int k = 0; k < SCAN_CH; k++) {
        int i = start + k;
        if (i < NA) s += g_cnt[i];
    }
    sh[t] = s;
    __syncthreads();
    for (int off = 1; off < SCAN_T; off <<= 1) {
        int v = (t >= off) ? sh[t - off] : 0;
        __syncthreads();
        sh[t] += v;
        __syncthreads();
    }
    int base = (t == 0) ? 0 : sh[t - 1];
#pragma unroll
    for (int k = 0; k < SCAN_CH; k++) {
        int i = start + k;
        if (i < NA) {
            g_head[i] = base;
            base += g_cnt[i];
        }
    }
}

__global__ void scatter_kernel(const int* __restrict__ idx_i, const int* __restrict__ idx_j) {
    int e = blockIdx.x * blockDim.x + threadIdx.x;
    if (e >= NE) return;
    int i = idx_i[e];
    int pos = atomicAdd(&g_head[i], 1);
    g_perm[e] = pos;
    g_is[pos] = i;
    g_js[pos] = idx_j[e];
}

// geometry written at sorted positions, phi split to padded bf16
__global__ void geom_kernel(const float* __restrict__ rij) {
    int e = blockIdx.x * blockDim.x + threadIdx.x;
    if (e >= NE) return;
    int p = g_perm[e];
    float r0 = rij[e * 3 + 0], r1 = rij[e * 3 + 1], r2 = rij[e * 3 + 2];
    float d = sqrtf(r0 * r0 + r1 * r1 + r2 * r2);
    float inv = 1.0f / d;
    float fc = (d < CUTOFF) ? 0.5f * (cosf(d * PI_F / CUTOFF) + 1.0f) : 0.0f;
    g_dirfS[p] = make_float4(r0 * inv, r1 * inv, r2 * inv, fc);
    const float width = CUTOFF / (NRBF - 1);
    const float coeff = -0.5f / (width * width);
    __nv_bfloat16* ph = g_phh + (size_t)p * 32;
    __nv_bfloat16* pl = g_phl + (size_t)p * 32;
#pragma unroll
    for (int k = 0; k < 32; k++) {
        float v;
        if (k < NRBF) {
            float t = d - width * k;
            v = expf(coeff * t * t) * fc;
        } else if (k == NRBF) {
            v = fc;  // bias row
        } else {
            v = 0.0f;
        }
        __nv_bfloat16 h = __float2bfloat16(v);
        ph[k] = h;
        pl[k] = __float2bfloat16(v - __bfloat162float(h));
    }
}

// filter weights: [l][n][k]; k<20 from filt_W, k==20 = bias, else 0
__global__ void fwprep_kernel(const float* __restrict__ W, const float* __restrict__ b) {
    int i = blockIdx.x * blockDim.x + threadIdx.x;
    if (i >= NL * 384 * 32) return;
    int l = i / (384 * 32), r = i % (384 * 32);
    int n = r >> 5, k = r & 31;
    float v = 0.0f;
    if (k < NRBF) v = W[k * (NL * 384) + l * 384 + n];
    else if (k == NRBF) v = b[l * 384 + n];
    __nv_bfloat16 h = __float2bfloat16(v);
    g_FWh[i] = h;
    g_FWl[i] = __float2bfloat16(v - __bfloat162float(h));
}

// GEMM weights transpose+split (all layers)
__global__ void wprep_kernel(const float* __restrict__ src, int K, int N, int dstoff) {
    int i = blockIdx.x * blockDim.x + threadIdx.x;
    if (i >= NL * K * N) return;
    int l = i / (K * N), r = i % (K * N);
    int n = r / K, k = r % K;
    float v = src[(size_t)l * K * N + (size_t)k * N + n];
    __nv_bfloat16 h = __float2bfloat16(v);
    g_Bhi[l * WL + dstoff + r] = h;
    g_Blo[l * WL + dstoff + r] = __float2bfloat16(v - __bfloat162float(h));
}

// =================== mma helpers ===================
__device__ __forceinline__ void ldm_x4(uint32_t* r, uint32_t addr) {
    asm volatile("ldmatrix.sync.aligned.m8n8.x4.shared.b16 {%0,%1,%2,%3}, [%4];"
                 : "=r"(r[0]), "=r"(r[1]), "=r"(r[2]), "=r"(r[3]) : "r"(addr));
}
__device__ __forceinline__ void ldm_x2(uint32_t* r, uint32_t addr) {
    asm volatile("ldmatrix.sync.aligned.m8n8.x2.shared.b16 {%0,%1}, [%2];"
                 : "=r"(r[0]), "=r"(r[1]) : "r"(addr));
}
__device__ __forceinline__ void mma_bf16(float* d, const uint32_t* a, const uint32_t* b) {
    asm volatile(
        "mma.sync.aligned.m16n8k16.row.col.f32.bf16.bf16.f32 "
        "{%0,%1,%2,%3}, {%4,%5,%6,%7}, {%8,%9}, {%0,%1,%2,%3};"
        : "+f"(d[0]), "+f"(d[1]), "+f"(d[2]), "+f"(d[3])
        : "r"(a[0]), "r"(a[1]), "r"(a[2]), "r"(a[3]), "r"(b[0]), "r"(b[1]));
}
__device__ __forceinline__ uint32_t smem_u32(const void* p) {
    uint32_t a;
    asm("{ .reg .u64 t; cvta.to.shared.u64 t, %1; cvt.u32.u64 %0, t; }" : "=r"(a) : "l"(p));
    return a;
}

// =================== fused tensor-filter + CSR edge kernel ===================
// 256 threads: f = tid&127, parity p = tid>>7. ET=256 edges/block, subtiles of 32.
#define ET 256
#define EGRID ((NE + ET - 1) / ET)
// smem offsets
#define SO_WH 0
#define SO_WL 24576
#define SO_PH 49152
#define SO_PL 51200
#define SO_F  53248
#define SO_IS 102400
#define SO_JS 103424
#define EDGE_SMEM 104448

__global__ void __launch_bounds__(256) edge_kernel(int layer,
                                                   const float* __restrict__ mu,
                                                   float* __restrict__ q) {
    extern __shared__ char sm[];
    __nv_bfloat16* sWh = (__nv_bfloat16*)(sm + SO_WH);
    __nv_bfloat16* sWl = (__nv_bfloat16*)(sm + SO_WL);
    __nv_bfloat16* sPh = (__nv_bfloat16*)(sm + SO_PH);
    __nv_bfloat16* sPl = (__nv_bfloat16*)(sm + SO_PL);
    float* sF = (float*)(sm + SO_F);
    int* s_is = (int*)(sm + SO_IS);
    int* s_js = (int*)(sm + SO_JS);

    int tid = threadIdx.x;
    int wid = tid >> 5, lane = tid & 31;
    int base = blockIdx.x * ET;
    const uint4 z4 = make_uint4(0, 0, 0, 0);

    // stage filter weights (12288 bf16 = 1536 uint4 per buffer)
    {
        const uint4* gh = (const uint4*)(g_FWh + layer * 12288);
        const uint4* gl = (const uint4*)(g_FWl + layer * 12288);
        for (int i = tid; i < 1536; i += 256) {
            ((uint4*)sWh)[i] = __ldg(gh + i);
            ((uint4*)sWl)[i] = __ldg(gl + i);
        }
    }
    // stage sorted i/j
    {
        int pos = base + tid;
        s_is[tid] = (pos < NE) ? __ldg(g_is + pos) : INT_MAX;
        s_js[tid] = (pos < NE) ? __ldg(g_js + pos) : 0;
    }
    __syncthreads();

    int f = tid & 127;
    int par = tid >> 7;
    int wm = wid & 1, wn = wid >> 1;  // 8 warps: 2(m) x 4(n)
    int curi = -1;
    float accq = 0.f, ac0 = 0.f, ac1 = 0.f, ac2 = 0.f;

    for (int sub = 0; sub < ET / 32; sub++) {
        int sb = base + sub * 32;
        if (sb >= NE) break;
        // stage phi subtile: 32 rows x 32 bf16 (4 uint4/row) per buffer
        {
            int row = tid & 31;
            int c4 = (tid >> 5) & 3;  // 0..3
            int buf = tid >> 7;       // 0=hi, 1=lo
            int p = sb + row;
            if (buf == 0) {
                uint4 v = (p < NE) ? __ldg((const uint4*)(g_phh + (size_t)p * 32) + c4) : z4;
                ((uint4*)sPh)[row * 4 + c4] = v;
            } else {
                uint4 v = (p < NE) ? __ldg((const uint4*)(g_phl + (size_t)p * 32) + c4) : z4;
                ((uint4*)sPl)[row * 4 + c4] = v;
            }
        }
        __syncthreads();
        // tensor-core filter GEMM: sF[32][384] = phi(32x32) @ Wt(384x32)^T, 3-term
        {
            uint32_t aPh = smem_u32(sPh + wm * 16 * 32);
            uint32_t aPl = smem_u32(sPl + wm * 16 * 32);
            uint32_t aoff0 = ((lane & 15) * 32 + 0 + ((lane >> 4) << 3)) * 2;
            uint32_t aoff1 = ((lane & 15) * 32 + 16 + ((lane >> 4) << 3)) * 2;
            uint32_t ah0[4], ah1[4], al0[4], al1[4];
            ldm_x4(ah0, aPh + aoff0);
            ldm_x4(ah1, aPh + aoff1);
            ldm_x4(al0, aPl + aoff0);
            ldm_x4(al1, aPl + aoff1);
            uint32_t bWh = smem_u32(sWh), bWl = smem_u32(sWl);
            uint32_t lrow = ((lane & 7) * 32 + (((lane >> 3) & 1) << 3)) * 2;
#pragma unroll
            for (int nt = 0; nt < 12; nt++) {
                int n0 = wn * 96 + nt * 8;
                uint32_t boff0 = (uint32_t)(n0 * 64) + lrow;
                uint32_t boff1 = boff0 + 32;
                uint32_t bh0[2], bh1[2], bl0[2], bl1[2];
                ldm_x2(bh0, bWh + boff0);
                ldm_x2(bh1, bWh + boff1);
                ldm_x2(bl0, bWl + boff0);
                ldm_x2(bl1, bWl + boff1);
                float acc[4] = {0.f, 0.f, 0.f, 0.f};
                mma_bf16(acc, ah0, bh0);
                mma_bf16(acc, ah1, bh1);
                mma_bf16(acc, ah0, bl0);
                mma_bf16(acc, ah1, bl1);
                mma_bf16(acc, al0, bh0);
                mma_bf16(acc, al1, bh1);
                int r = wm * 16 + (lane >> 2);
                int cc = n0 + (lane & 3) * 2;
                *(float2*)&sF[r * 384 + cc] = make_float2(acc[0], acc[1]);
                *(float2*)&sF[(r + 8) * 384 + cc] = make_float2(acc[2], acc[3]);
            }
        }
        __syncthreads();
        // message phase: parity p handles t = par, par+2, ...
        int nEt = min(32, NE - sb);
        for (int t = par; t < nEt; t += 2) {
            int i = s_is[sub * 32 + t];
            int j = s_js[sub * 32 + t];
            if (i != curi) {
                if (curi >= 0) {
                    atomicAdd(q + curi * 128 + f, accq);
                    atomicAdd(g_dmu + curi * 384 + f, ac0);
                    atomicAdd(g_dmu + curi * 384 + 128 + f, ac1);
                    atomicAdd(g_dmu + curi * 384 + 256 + f, ac2);
                }
                curi = i;
                accq = ac0 = ac1 = ac2 = 0.f;
            }
            float4 dfv = __ldg(g_dirfS + sb + t);
            const float* xj = g_x + j * 384;
            const float* mj = mu + j * 384;
            float x0 = __ldg(xj + f), x1 = __ldg(xj + 128 + f), x2 = __ldg(xj + 256 + f);
            float m0 = __ldg(mj + f), m1 = __ldg(mj + 128 + f), m2 = __ldg(mj + 256 + f);
            float F0 = sF[t * 384 + f], F1 = sF[t * 384 + 128 + f], F2 = sF[t * 384 + 256 + f];
            float dmuR = F1 * x1;
            float dmm = F2 * x2;
            accq += F0 * x0;
            ac0 += dmuR * dfv.x + dmm * m0;
            ac1 += dmuR * dfv.y + dmm * m1;
            ac2 += dmuR * dfv.z + dmm * m2;
        }
        __syncthreads();
    }
    if (curi >= 0) {
        atomicAdd(q + curi * 128 + f, accq);
        atomicAdd(g_dmu + curi * 384 + f, ac0);
        atomicAdd(g_dmu + curi * 384 + 128 + f, ac1);
        atomicAdd(g_dmu + curi * 384 + 256 + f, ac2);
    }
}

// mu += dmu; dmu = 0; emit mu hi/lo split
__global__ void addmu_kernel(float* __restrict__ mu) {
    int i = (blockIdx.x * blockDim.x + threadIdx.x) * 2;
    if (i >= NA * 384) return;
    float v0 = mu[i] + g_dmu[i];
    float v1 = mu[i + 1] + g_dmu[i + 1];
    mu[i] = v0;
    mu[i + 1] = v1;
    g_dmu[i] = 0.0f;
    g_dmu[i + 1] = 0.0f;
    split_store(g_muhi, g_mulo, i, v0, v1);
}

// =================== bf16x3 GEMM (proven, unchanged) ===================
#define AS 40
__global__ void __launch_bounds__(256) gemm_mma(const __nv_bfloat16* __restrict__ Ahi,
                                                const __nv_bfloat16* __restrict__ Alo,
                                                const __nv_bfloat16* __restrict__ Bhi,
                                                const __nv_bfloat16* __restrict__ Blo,
                                                const float* __restrict__ bias,
                                                float* __restrict__ C,
                                                __nv_bfloat16* __restrict__ Shi,
                                                __nv_bfloat16* __restrict__ Slo,
                                                int M, int N, int K, int act) {
    __shared__ __nv_bfloat16 sAh[128][AS], sAl[128][AS], sBh[128][AS], sBl[128][AS];
    int tid = threadIdx.x;
    int wid = tid >> 5, lane = tid & 31;
    int wm = wid & 3, wn = wid >> 2;
    int row0 = blockIdx.y * 128, col0 = blockIdx.x * 128;

    float acc[2][8][4];
#pragma unroll
    for (int i = 0; i < 2; i++)
#pragma unroll
        for (int j = 0; j < 8; j++)
#pragma unroll
            for (int k = 0; k < 4; k++) acc[i][j][k] = 0.f;

    int lrow = tid >> 1, lcol = (tid & 1) << 4;
    bool rowok = (row0 + lrow) < M;
    const __nv_bfloat16* pAh = Ahi + (size_t)(row0 + lrow) * K + lcol;
    const __nv_bfloat16* pAl = Alo + (size_t)(row0 + lrow) * K + lcol;
    const __nv_bfloat16* pBh = Bhi + (size_t)(col0 + lrow) * K + lcol;
    const __nv_bfloat16* pBl = Blo + (size_t)(col0 + lrow) * K + lcol;
    const uint4 z4 = make_uint4(0, 0, 0, 0);

    uint32_t aAh = smem_u32(&sAh[wm * 32][0]);
    uint32_t aAl = smem_u32(&sAl[wm * 32][0]);
    uint32_t aBh = smem_u32(&sBh[wn * 64][0]);
    uint32_t aBl = smem_u32(&sBl[wn * 64][0]);

    for (int c = 0; c < (K >> 5); c++) {
#pragma unroll
        for (int u = 0; u < 2; u++) {
            int co = c * 32 + u * 8;
            *(uint4*)&sAh[lrow][lcol + u * 8] = rowok ? *(const uint4*)(pAh + co) : z4;
            *(uint4*)&sAl[lrow][lcol + u * 8] = rowok ? *(const uint4*)(pAl + co) : z4;
            *(uint4*)&sBh[lrow][lcol + u * 8] = *(const uint4*)(pBh + co);
            *(uint4*)&sBl[lrow][lcol + u * 8] = *(const uint4*)(pBl + co);
        }
        __syncthreads();
#pragma unroll
        for (int ks = 0; ks < 2; ks++) {
            int kk = ks * 16;
            uint32_t ah[2][4], al[2][4];
            uint32_t aoff = ((lane & 15) * AS + kk + ((lane >> 4) << 3)) * 2;
#pragma unroll
            for (int mt = 0; mt < 2; mt++) {
                ldm_x4(ah[mt], aAh + mt * 16 * AS * 2 + aoff);
                ldm_x4(al[mt], aAl + mt * 16 * AS * 2 + aoff);
            }
            uint32_t boff = ((lane & 7) * AS + kk + (((lane >> 3) & 1) << 3)) * 2;
#pragma unroll
            for (int nt = 0; nt < 8; nt++) {
                uint32_t bh[2], bl[2];
                ldm_x2(bh, aBh + nt * 8 * AS * 2 + boff);
                ldm_x2(bl, aBl + nt * 8 * AS * 2 + boff);
#pragma unroll
                for (int mt = 0; mt < 2; mt++) {
                    mma_bf16(acc[mt][nt], ah[mt], bh);
                    mma_bf16(acc[mt][nt], ah[mt], bl);
                    mma_bf16(acc[mt][nt], al[mt], bh);
                }
            }
        }
        __syncthreads();
    }

    int gid = lane >> 2, tig = lane & 3;
#pragma unroll
    for (int mt = 0; mt < 2; mt++) {
#pragma unroll
        for (int nt = 0; nt < 8; nt++) {
            int cc = col0 + wn * 64 + nt * 8 + tig * 2;
            float b0 = __ldg(bias + cc), b1 = __ldg(bias + cc + 1);
            int r0 = row0 + wm * 32 + mt * 16 + gid;
            float v0 = acc[mt][nt][0] + b0, v1 = acc[mt][nt][1] + b1;
            float v2 = acc[mt][nt][2] + b0, v3 = acc[mt][nt][3] + b1;
            if (act) {
                v0 = v0 / (1.0f + expf(-v0));
                v1 = v1 / (1.0f + expf(-v1));
                v2 = v2 / (1.0f + expf(-v2));
                v3 = v3 / (1.0f + expf(-v3));
            }
            if (r0 < M) {
                size_t o = (size_t)r0 * N + cc;
                if (C) *(float2*)(C + o) = make_float2(v0, v1);
                if (Shi) split_store(Shi, Slo, o, v0, v1);
            }
            if (r0 + 8 < M) {
                size_t o = (size_t)(r0 + 8) * N + cc;
                if (C) *(float2*)(C + o) = make_float2(v2, v3);
                if (Shi) split_store(Shi, Slo, o, v2, v3);
            }
        }
    }
}

// =================== ctx / update ===================
__global__ void ctx_kernel(const float* __restrict__ q) {
    int i = (blockIdx.x * blockDim.x + threadIdx.x) * 2;
    if (i >= NA * FF) return;
    int a = i >> 7, f = i & 127;
    float v0 = g_mumix[(a * 3 + 0) * 256 + f];
    float v1 = g_mumix[(a * 3 + 1) * 256 + f];
    float v2 = g_mumix[(a * 3 + 2) * 256 + f];
    float n0 = sqrtf(v0 * v0 + v1 * v1 + v2 * v2);
    float u0 = g_mumix[(a * 3 + 0) * 256 + f + 1];
    float u1 = g_mumix[(a * 3 + 1) * 256 + f + 1];
    float u2 = g_mumix[(a * 3 + 2) * 256 + f + 1];
    float n1 = sqrtf(u0 * u0 + u1 * u1 + u2 * u2);
    split_store(g_chi, g_clo, (size_t)a * 256 + f, q[i], q[i + 1]);
    split_store(g_chi, g_clo, (size_t)a * 256 + 128 + f, n0, n1);
}

__global__ void update_kernel(float* __restrict__ q, float* __restrict__ mu) {
    int i = (blockIdx.x * blockDim.x + threadIdx.x) * 2;
    if (i >= NA * FF) return;
    int a = i >> 7, f = i & 127;
    float s0 = 0.0f, s1 = 0.0f;
    float xmu0 = g_x[a * 384 + 128 + f], xmu1 = g_x[a * 384 + 128 + f + 1];
#pragma unroll
    for (int d = 0; d < 3; d++) {
        float mv0 = g_mumix[(a * 3 + d) * 256 + f];
        float mw0 = g_mumix[(a * 3 + d) * 256 + 128 + f];
        float mv1 = g_mumix[(a * 3 + d) * 256 + f + 1];
        float mw1 = g_mumix[(a * 3 + d) * 256 + 128 + f + 1];
        s0 += mv0 * mw0;
        s1 += mv1 * mw1;
        mu[a * 384 + d * 128 + f] += xmu0 * mw0;
        mu[a * 384 + d * 128 + f + 1] += xmu1 * mw1;
    }
    float q0 = q[i] + g_x[a * 384 + f] + g_x[a * 384 + 256 + f] * s0;
    float q1 = q[i + 1] + g_x[a * 384 + f + 1] + g_x[a * 384 + 256 + f + 1] * s1;
    q[i] = q0;
    q[i + 1] = q1;
    split_store(g_qhi, g_qlo, i, q0, q1);
}

// =================== launcher ===================
extern "C" void kernel_launch(void* const* d_in, const int* in_sizes, int n_in,
                              void* d_out, int out_size) {
    const float* r_ij      = (const float*)d_in[0];
    const float* embedding = (const float*)d_in[1];
    const float* filt_W    = (const float*)d_in[2];
    const float* filt_b    = (const float*)d_in[3];
    const float* inter_W1  = (const float*)d_in[4];
    const float* inter_b1  = (const float*)d_in[5];
    const float* inter_W2  = (const float*)d_in[6];
    const float* inter_b2  = (const float*)d_in[7];
    const float* mix_W     = (const float*)d_in[8];
    const float* mix_b     = (const float*)d_in[9];
    const float* intra_W1  = (const float*)d_in[10];
    const float* intra_b1  = (const float*)d_in[11];
    const float* intra_W2  = (const float*)d_in[12];
    const float* intra_b2  = (const float*)d_in[13];
    const int*   z         = (const int*)d_in[14];
    const int*   idx_i     = (const int*)d_in[15];
    const int*   idx_j     = (const int*)d_in[16];

    float* q  = (float*)d_out;
    float* mu = q + (size_t)NA * FF;

    cudaFuncSetAttribute(edge_kernel, cudaFuncAttributeMaxDynamicSharedMemorySize, EDGE_SMEM);

    void *p_x, *p_mumix, *p_qhi, *p_qlo, *p_hhi, *p_hlo, *p_muhi, *p_mulo, *p_chi, *p_clo,
        *p_Bhi, *p_Blo;
    cudaGetSymbolAddress(&p_x, g_x);
    cudaGetSymbolAddress(&p_mumix, g_mumix);
    cudaGetSymbolAddress(&p_qhi, g_qhi);
    cudaGetSymbolAddress(&p_qlo, g_qlo);
    cudaGetSymbolAddress(&p_hhi, g_hhi);
    cudaGetSymbolAddress(&p_hlo, g_hlo);
    cudaGetSymbolAddress(&p_muhi, g_muhi);
    cudaGetSymbolAddress(&p_mulo, g_mulo);
    cudaGetSymbolAddress(&p_chi, g_chi);
    cudaGetSymbolAddress(&p_clo, g_clo);
    cudaGetSymbolAddress(&p_Bhi, g_Bhi);
    cudaGetSymbolAddress(&p_Blo, g_Blo);
    float* xbuf  = (float*)p_x;
    float* mumix = (float*)p_mumix;
    __nv_bfloat16 *qhi = (__nv_bfloat16*)p_qhi, *qlo = (__nv_bfloat16*)p_qlo;
    __nv_bfloat16 *hhi = (__nv_bfloat16*)p_hhi, *hlo = (__nv_bfloat16*)p_hlo;
    __nv_bfloat16 *muhi = (__nv_bfloat16*)p_muhi, *mulo = (__nv_bfloat16*)p_mulo;
    __nv_bfloat16 *chi = (__nv_bfloat16*)p_chi, *clo = (__nv_bfloat16*)p_clo;
    __nv_bfloat16 *Bhi = (__nv_bfloat16*)p_Bhi, *Blo = (__nv_bfloat16*)p_Blo;

    init_kernel<<<(NA * 384 + 255) / 256, 256>>>(z, embedding, q, mu);
    hist_kernel<<<(NE + 255) / 256, 256>>>(idx_i);
    scan_kernel<<<1, SCAN_T>>>();
    scatter_kernel<<<(NE + 255) / 256, 256>>>(idx_i, idx_j);
    geom_kernel<<<(NE + 255) / 256, 256>>>(r_ij);
    fwprep_kernel<<<(NL * 384 * 32 + 255) / 256, 256>>>(filt_W, filt_b);
    wprep_kernel<<<(NL * 128 * 128 + 255) / 256, 256>>>(inter_W1, 128, 128, 0);
    wprep_kernel<<<(NL * 128 * 384 + 255) / 256, 256>>>(inter_W2, 128, 384, 16384);
    wprep_kernel<<<(NL * 128 * 256 + 255) / 256, 256>>>(mix_W, 128, 256, 65536);
    wprep_kernel<<<(NL * 256 * 128 + 255) / 256, 256>>>(intra_W1, 256, 128, 98304);
    wprep_kernel<<<(NL * 128 * 384 + 255) / 256, 256>>>(intra_W2, 128, 384, 131072);

    for (int l = 0; l < NL; l++) {
        int wb = l * WL;
        // h = silu(q @ W1 + b1) -> split only
        gemm_mma<<<dim3(1, (NA + 127) / 128), 256>>>(
            qhi, qlo, Bhi + wb, Blo + wb, inter_b1 + l * 128,
            nullptr, hhi, hlo, NA, 128, 128, 1);
        // x = h @ W2 + b2 -> fp32
        gemm_mma<<<dim3(3, (NA + 127) / 128), 256>>>(
            hhi, hlo, Bhi + wb + 16384, Blo + wb + 16384, inter_b2 + l * 384,
            xbuf, nullptr, nullptr, NA, 384, 128, 0);
        // fused tensor-filter + CSR edge messages
        edge_kernel<<<EGRID, 256, EDGE_SMEM>>>(l, mu, q);
        // mu += dmu (emit mu split)
        addmu_kernel<<<(NA * 192 + 255) / 256, 256>>>(mu);
        // mu_mix = mu @ mix_W + mix_b -> fp32
        gemm_mma<<<dim3(2, (NA * 3 + 127) / 128), 256>>>(
            muhi, mulo, Bhi + wb + 65536, Blo + wb + 65536, mix_b + l * 256,
            mumix, nullptr, nullptr, NA * 3, 256, 128, 0);
        // ctx = [q, ||mu_V||] -> split only
        ctx_kernel<<<(NA * 64 + 255) / 256, 256>>>(q);
        // h = silu(ctx @ intra_W1 + b1) -> split only
        gemm_mma<<<dim3(1, (NA + 127) / 128), 256>>>(
            chi, clo, Bhi + wb + 98304, Blo + wb + 98304, intra_b1 + l * 128,
            nullptr, hhi, hlo, NA, 128, 256, 1);
        // x = h @ intra_W2 + b2 -> fp32
        gemm_mma<<<dim3(3, (NA + 127) / 128), 256>>>(
            hhi, hlo, Bhi + wb + 131072, Blo + wb + 131072, intra_b2 + l * 384,
            xbuf, nullptr, nullptr, NA, 384, 128, 0);
        // q += dq_intra + dqmu_intra (emit q split); mu += dmu_intra
        update_kernel<<<(NA * 64 + 255) / 256, 256>>>(q, mu);
    }
}

// round 10
// speedup vs baseline: 1.3983x; 1.0365x over previous
#include <cuda_runtime.h>
#include <cuda_bf16.h>
#include <math.h>
#include <stdint.h>

#define NA 15000
#define NE 300000
#define FF 128
#define NRBF 20
#define NL 3
#define CUTOFF 5.0f
#define PI_F 3.14159265358979f

// =================== static scratch ===================
__device__ float4 g_dirf[NE];                     // (dir.xyz, fcut)
__device__ __nv_bfloat16 g_phh[(size_t)NE * 32];  // padded phi hi (k20=fcut, 21..31=0)
__device__ __nv_bfloat16 g_phl[(size_t)NE * 32];  // phi lo
__device__ float g_filt[(size_t)NE * 384];        // per-edge filters (fp32, one layer at a time)
__device__ float g_x[NA * 384];
__device__ float g_mumix[NA * 3 * 256];
__device__ float g_dmu[NA * 384];
__device__ float g_zeros[384];                    // zero bias (bss-zeroed)
// bf16 hi/lo split operands
__device__ __nv_bfloat16 g_qhi[NA * 128], g_qlo[NA * 128];
__device__ __nv_bfloat16 g_hhi[NA * 128], g_hlo[NA * 128];
__device__ __nv_bfloat16 g_muhi[NA * 384], g_mulo[NA * 384];
__device__ __nv_bfloat16 g_chi[NA * 256], g_clo[NA * 256];
#define WL 180224
__device__ __nv_bfloat16 g_Bhi[NL * WL];
__device__ __nv_bfloat16 g_Blo[NL * WL];
// filter weights transposed+padded: [l][n=384][k=32]
__device__ __nv_bfloat16 g_FWh[NL * 384 * 32];
__device__ __nv_bfloat16 g_FWl[NL * 384 * 32];

__device__ __forceinline__ void split_store(__nv_bfloat16* hi, __nv_bfloat16* lo,
                                            size_t off, float v0, float v1) {
    __nv_bfloat16 h0 = __float2bfloat16(v0), h1 = __float2bfloat16(v1);
    __nv_bfloat162 H, L;
    H.x = h0; H.y = h1;
    L.x = __float2bfloat16(v0 - __bfloat162float(h0));
    L.y = __float2bfloat16(v1 - __bfloat162float(h1));
    *(__nv_bfloat162*)(hi + off) = H;
    *(__nv_bfloat162*)(lo + off) = L;
}

// =================== prep kernels ===================
__global__ void init_kernel(const int* __restrict__ z, const float* __restrict__ emb,
                            float* __restrict__ q, float* __restrict__ mu) {
    int i = blockIdx.x * blockDim.x + threadIdx.x;
    if (i >= NA * 384) return;
    mu[i] = 0.0f;
    g_dmu[i] = 0.0f;
    if (i < NA * FF) {
        int a = i >> 7, f = i & 127;
        float v = emb[z[a] * FF + f];
        q[i] = v;
        __nv_bfloat16 h = __float2bfloat16(v);
        g_qhi[i] = h;
        g_qlo[i] = __float2bfloat16(v - __bfloat162float(h));
    }
}

// geometry: dirf + padded split phi (k20 = fcut carries the bias row)
__global__ void geom_kernel(const float* __restrict__ rij) {
    int e = blockIdx.x * blockDim.x + threadIdx.x;
    if (e >= NE) return;
    float r0 = rij[e * 3 + 0], r1 = rij[e * 3 + 1], r2 = rij[e * 3 + 2];
    float d = sqrtf(r0 * r0 + r1 * r1 + r2 * r2);
    float inv = 1.0f / d;
    float fc = (d < CUTOFF) ? 0.5f * (cosf(d * PI_F / CUTOFF) + 1.0f) : 0.0f;
    g_dirf[e] = make_float4(r0 * inv, r1 * inv, r2 * inv, fc);
    const float width = CUTOFF / (NRBF - 1);
    const float coeff = -0.5f / (width * width);
    __nv_bfloat16* ph = g_phh + (size_t)e * 32;
    __nv_bfloat16* pl = g_phl + (size_t)e * 32;
#pragma unroll
    for (int k = 0; k < 32; k++) {
        float v;
        if (k < NRBF) {
            float t = d - width * k;
            v = expf(coeff * t * t) * fc;
        } else if (k == NRBF) {
            v = fc;
        } else {
            v = 0.0f;
        }
        __nv_bfloat16 h = __float2bfloat16(v);
        ph[k] = h;
        pl[k] = __float2bfloat16(v - __bfloat162float(h));
    }
}

// filter weights: [l][n][k]; k<20 from filt_W, k==20 = bias, else 0
__global__ void fwprep_kernel(const float* __restrict__ W, const float* __restrict__ b) {
    int i = blockIdx.x * blockDim.x + threadIdx.x;
    if (i >= NL * 384 * 32) return;
    int l = i / (384 * 32), r = i % (384 * 32);
    int n = r >> 5, k = r & 31;
    float v = 0.0f;
    if (k < NRBF) v = W[k * (NL * 384) + l * 384 + n];
    else if (k == NRBF) v = b[l * 384 + n];
    __nv_bfloat16 h = __float2bfloat16(v);
    g_FWh[i] = h;
    g_FWl[i] = __float2bfloat16(v - __bfloat162float(h));
}

// GEMM weights transpose+split (all layers)
__global__ void wprep_kernel(const float* __restrict__ src, int K, int N, int dstoff) {
    int i = blockIdx.x * blockDim.x + threadIdx.x;
    if (i >= NL * K * N) return;
    int l = i / (K * N), r = i % (K * N);
    int n = r / K, k = r % K;
    float v = src[(size_t)l * K * N + (size_t)k * N + n];
    __nv_bfloat16 h = __float2bfloat16(v);
    g_Bhi[l * WL + dstoff + r] = h;
    g_Blo[l * WL + dstoff + r] = __float2bfloat16(v - __bfloat162float(h));
}

// =================== mma helpers ===================
__device__ __forceinline__ void ldm_x4(uint32_t* r, uint32_t addr) {
    asm volatile("ldmatrix.sync.aligned.m8n8.x4.shared.b16 {%0,%1,%2,%3}, [%4];"
                 : "=r"(r[0]), "=r"(r[1]), "=r"(r[2]), "=r"(r[3]) : "r"(addr));
}
__device__ __forceinline__ void ldm_x2(uint32_t* r, uint32_t addr) {
    asm volatile("ldmatrix.sync.aligned.m8n8.x2.shared.b16 {%0,%1}, [%2];"
                 : "=r"(r[0]), "=r"(r[1]) : "r"(addr));
}
__device__ __forceinline__ void mma_bf16(float* d, const uint32_t* a, const uint32_t* b) {
    asm volatile(
        "mma.sync.aligned.m16n8k16.row.col.f32.bf16.bf16.f32 "
        "{%0,%1,%2,%3}, {%4,%5,%6,%7}, {%8,%9}, {%0,%1,%2,%3};"
        : "+f"(d[0]), "+f"(d[1]), "+f"(d[2]), "+f"(d[3])
        : "r"(a[0]), "r"(a[1]), "r"(a[2]), "r"(a[3]), "r"(b[0]), "r"(b[1]));
}
__device__ __forceinline__ uint32_t smem_u32(const void* p) {
    uint32_t a;
    asm("{ .reg .u64 t; cvta.to.shared.u64 t, %1; cvt.u32.u64 %0, t; }" : "=r"(a) : "l"(p));
    return a;
}

// =================== bf16x3 GEMM (proven) ===================
#define AS 40
__global__ void __launch_bounds__(256) gemm_mma(const __nv_bfloat16* __restrict__ Ahi,
                                                const __nv_bfloat16* __restrict__ Alo,
                                                const __nv_bfloat16* __restrict__ Bhi,
                                                const __nv_bfloat16* __restrict__ Blo,
                                                const float* __restrict__ bias,
                                                float* __restrict__ C,
                                                __nv_bfloat16* __restrict__ Shi,
                                                __nv_bfloat16* __restrict__ Slo,
                                                int M, int N, int K, int act) {
    __shared__ __nv_bfloat16 sAh[128][AS], sAl[128][AS], sBh[128][AS], sBl[128][AS];
    int tid = threadIdx.x;
    int wid = tid >> 5, lane = tid & 31;
    int wm = wid & 3, wn = wid >> 2;
    int row0 = blockIdx.y * 128, col0 = blockIdx.x * 128;

    float acc[2][8][4];
#pragma unroll
    for (int i = 0; i < 2; i++)
#pragma unroll
        for (int j = 0; j < 8; j++)
#pragma unroll
            for (int k = 0; k < 4; k++) acc[i][j][k] = 0.f;

    int lrow = tid >> 1, lcol = (tid & 1) << 4;
    bool rowok = (row0 + lrow) < M;
    const __nv_bfloat16* pAh = Ahi + (size_t)(row0 + lrow) * K + lcol;
    const __nv_bfloat16* pAl = Alo + (size_t)(row0 + lrow) * K + lcol;
    const __nv_bfloat16* pBh = Bhi + (size_t)(col0 + lrow) * K + lcol;
    const __nv_bfloat16* pBl = Blo + (size_t)(col0 + lrow) * K + lcol;
    const uint4 z4 = make_uint4(0, 0, 0, 0);

    uint32_t aAh = smem_u32(&sAh[wm * 32][0]);
    uint32_t aAl = smem_u32(&sAl[wm * 32][0]);
    uint32_t aBh = smem_u32(&sBh[wn * 64][0]);
    uint32_t aBl = smem_u32(&sBl[wn * 64][0]);

    for (int c = 0; c < (K >> 5); c++) {
#pragma unroll
        for (int u = 0; u < 2; u++) {
            int co = c * 32 + u * 8;
            *(uint4*)&sAh[lrow][lcol + u * 8] = rowok ? *(const uint4*)(pAh + co) : z4;
            *(uint4*)&sAl[lrow][lcol + u * 8] = rowok ? *(const uint4*)(pAl + co) : z4;
            *(uint4*)&sBh[lrow][lcol + u * 8] = *(const uint4*)(pBh + co);
            *(uint4*)&sBl[lrow][lcol + u * 8] = *(const uint4*)(pBl + co);
        }
        __syncthreads();
#pragma unroll
        for (int ks = 0; ks < 2; ks++) {
            int kk = ks * 16;
            uint32_t ah[2][4], al[2][4];
            uint32_t aoff = ((lane & 15) * AS + kk + ((lane >> 4) << 3)) * 2;
#pragma unroll
            for (int mt = 0; mt < 2; mt++) {
                ldm_x4(ah[mt], aAh + mt * 16 * AS * 2 + aoff);
                ldm_x4(al[mt], aAl + mt * 16 * AS * 2 + aoff);
            }
            uint32_t boff = ((lane & 7) * AS + kk + (((lane >> 3) & 1) << 3)) * 2;
#pragma unroll
            for (int nt = 0; nt < 8; nt++) {
                uint32_t bh[2], bl[2];
                ldm_x2(bh, aBh + nt * 8 * AS * 2 + boff);
                ldm_x2(bl, aBl + nt * 8 * AS * 2 + boff);
#pragma unroll
                for (int mt = 0; mt < 2; mt++) {
                    mma_bf16(acc[mt][nt], ah[mt], bh);
                    mma_bf16(acc[mt][nt], ah[mt], bl);
                    mma_bf16(acc[mt][nt], al[mt], bh);
                }
            }
        }
        __syncthreads();
    }

    int gid = lane >> 2, tig = lane & 3;
#pragma unroll
    for (int mt = 0; mt < 2; mt++) {
#pragma unroll
        for (int nt = 0; nt < 8; nt++) {
            int cc = col0 + wn * 64 + nt * 8 + tig * 2;
            float b0 = __ldg(bias + cc), b1 = __ldg(bias + cc + 1);
            int r0 = row0 + wm * 32 + mt * 16 + gid;
            float v0 = acc[mt][nt][0] + b0, v1 = acc[mt][nt][1] + b1;
            float v2 = acc[mt][nt][2] + b0, v3 = acc[mt][nt][3] + b1;
            if (act) {
                v0 = v0 / (1.0f + expf(-v0));
                v1 = v1 / (1.0f + expf(-v1));
                v2 = v2 / (1.0f + expf(-v2));
                v3 = v3 / (1.0f + expf(-v3));
            }
            if (r0 < M) {
                size_t o = (size_t)r0 * N + cc;
                if (C) *(float2*)(C + o) = make_float2(v0, v1);
                if (Shi) split_store(Shi, Slo, o, v0, v1);
            }
            if (r0 + 8 < M) {
                size_t o = (size_t)(r0 + 8) * N + cc;
                if (C) *(float2*)(C + o) = make_float2(v2, v3);
                if (Shi) split_store(Shi, Slo, o, v2, v3);
            }
        }
    }
}

// =================== message kernel (branchless, max occupancy) ===================
__global__ void __launch_bounds__(128) msg_kernel(const float* __restrict__ F,
                                                  const int* __restrict__ idx_i,
                                                  const int* __restrict__ idx_j,
                                                  const float* __restrict__ mu,
                                                  float* __restrict__ q) {
    int f = threadIdx.x;
#pragma unroll 2
    for (int e = blockIdx.x; e < NE; e += gridDim.x) {
        int i = __ldg(idx_i + e), j = __ldg(idx_j + e);
        const float* Fe = F + (size_t)e * 384;
        float F0 = __ldg(Fe + f), F1 = __ldg(Fe + 128 + f), F2 = __ldg(Fe + 256 + f);
        float4 df = __ldg(g_dirf + e);
        const float* xj = g_x + j * 384;
        const float* mj = mu + j * 384;
        float dq   = F0 * __ldg(xj + f);
        float dmuR = F1 * __ldg(xj + 128 + f);
        float dmm  = F2 * __ldg(xj + 256 + f);
        atomicAdd(q + i * 128 + f, dq);
        atomicAdd(g_dmu + i * 384 + f,       dmuR * df.x + dmm * __ldg(mj + f));
        atomicAdd(g_dmu + i * 384 + 128 + f, dmuR * df.y + dmm * __ldg(mj + 128 + f));
        atomicAdd(g_dmu + i * 384 + 256 + f, dmuR * df.z + dmm * __ldg(mj + 256 + f));
    }
}

// mu += dmu; dmu = 0; emit mu hi/lo split
__global__ void addmu_kernel(float* __restrict__ mu) {
    int i = (blockIdx.x * blockDim.x + threadIdx.x) * 2;
    if (i >= NA * 384) return;
    float v0 = mu[i] + g_dmu[i];
    float v1 = mu[i + 1] + g_dmu[i + 1];
    mu[i] = v0;
    mu[i + 1] = v1;
    g_dmu[i] = 0.0f;
    g_dmu[i + 1] = 0.0f;
    split_store(g_muhi, g_mulo, i, v0, v1);
}

// =================== ctx / update ===================
__global__ void ctx_kernel(const float* __restrict__ q) {
    int i = (blockIdx.x * blockDim.x + threadIdx.x) * 2;
    if (i >= NA * FF) return;
    int a = i >> 7, f = i & 127;
    float v0 = g_mumix[(a * 3 + 0) * 256 + f];
    float v1 = g_mumix[(a * 3 + 1) * 256 + f];
    float v2 = g_mumix[(a * 3 + 2) * 256 + f];
    float n0 = sqrtf(v0 * v0 + v1 * v1 + v2 * v2);
    float u0 = g_mumix[(a * 3 + 0) * 256 + f + 1];
    float u1 = g_mumix[(a * 3 + 1) * 256 + f + 1];
    float u2 = g_mumix[(a * 3 + 2) * 256 + f + 1];
    float n1 = sqrtf(u0 * u0 + u1 * u1 + u2 * u2);
    split_store(g_chi, g_clo, (size_t)a * 256 + f, q[i], q[i + 1]);
    split_store(g_chi, g_clo, (size_t)a * 256 + 128 + f, n0, n1);
}

__global__ void update_kernel(float* __restrict__ q, float* __restrict__ mu) {
    int i = (blockIdx.x * blockDim.x + threadIdx.x) * 2;
    if (i >= NA * FF) return;
    int a = i >> 7, f = i & 127;
    float s0 = 0.0f, s1 = 0.0f;
    float xmu0 = g_x[a * 384 + 128 + f], xmu1 = g_x[a * 384 + 128 + f + 1];
#pragma unroll
    for (int d = 0; d < 3; d++) {
        float mv0 = g_mumix[(a * 3 + d) * 256 + f];
        float mw0 = g_mumix[(a * 3 + d) * 256 + 128 + f];
        float mv1 = g_mumix[(a * 3 + d) * 256 + f + 1];
        float mw1 = g_mumix[(a * 3 + d) * 256 + 128 + f + 1];
        s0 += mv0 * mw0;
        s1 += mv1 * mw1;
        mu[a * 384 + d * 128 + f] += xmu0 * mw0;
        mu[a * 384 + d * 128 + f + 1] += xmu1 * mw1;
    }
    float q0 = q[i] + g_x[a * 384 + f] + g_x[a * 384 + 256 + f] * s0;
    float q1 = q[i + 1] + g_x[a * 384 + f + 1] + g_x[a * 384 + 256 + f + 1] * s1;
    q[i] = q0;
    q[i + 1] = q1;
    split_store(g_qhi, g_qlo, i, q0, q1);
}

// =================== launcher ===================
extern "C" void kernel_launch(void* const* d_in, const int* in_sizes, int n_in,
                              void* d_out, int out_size) {
    const float* r_ij      = (const float*)d_in[0];
    const float* embedding = (const float*)d_in[1];
    const float* filt_W    = (const float*)d_in[2];
    const float* filt_b    = (const float*)d_in[3];
    const float* inter_W1  = (const float*)d_in[4];
    const float* inter_b1  = (const float*)d_in[5];
    const float* inter_W2  = (const float*)d_in[6];
    const float* inter_b2  = (const float*)d_in[7];
    const float* mix_W     = (const float*)d_in[8];
    const float* mix_b     = (const float*)d_in[9];
    const float* intra_W1  = (const float*)d_in[10];
    const float* intra_b1  = (const float*)d_in[11];
    const float* intra_W2  = (const float*)d_in[12];
    const float* intra_b2  = (const float*)d_in[13];
    const int*   z         = (const int*)d_in[14];
    const int*   idx_i     = (const int*)d_in[15];
    const int*   idx_j     = (const int*)d_in[16];

    float* q  = (float*)d_out;
    float* mu = q + (size_t)NA * FF;

    void *p_x, *p_mumix, *p_qhi, *p_qlo, *p_hhi, *p_hlo, *p_muhi, *p_mulo, *p_chi, *p_clo,
        *p_Bhi, *p_Blo, *p_FWh, *p_FWl, *p_phh, *p_phl, *p_filt, *p_zeros;
    cudaGetSymbolAddress(&p_x, g_x);
    cudaGetSymbolAddress(&p_mumix, g_mumix);
    cudaGetSymbolAddress(&p_qhi, g_qhi);
    cudaGetSymbolAddress(&p_qlo, g_qlo);
    cudaGetSymbolAddress(&p_hhi, g_hhi);
    cudaGetSymbolAddress(&p_hlo, g_hlo);
    cudaGetSymbolAddress(&p_muhi, g_muhi);
    cudaGetSymbolAddress(&p_mulo, g_mulo);
    cudaGetSymbolAddress(&p_chi, g_chi);
    cudaGetSymbolAddress(&p_clo, g_clo);
    cudaGetSymbolAddress(&p_Bhi, g_Bhi);
    cudaGetSymbolAddress(&p_Blo, g_Blo);
    cudaGetSymbolAddress(&p_FWh, g_FWh);
    cudaGetSymbolAddress(&p_FWl, g_FWl);
    cudaGetSymbolAddress(&p_phh, g_phh);
    cudaGetSymbolAddress(&p_phl, g_phl);
    cudaGetSymbolAddress(&p_filt, g_filt);
    cudaGetSymbolAddress(&p_zeros, g_zeros);
    float* xbuf  = (float*)p_x;
    float* mumix = (float*)p_mumix;
    float* filt  = (float*)p_filt;
    float* zeros = (float*)p_zeros;
    __nv_bfloat16 *qhi = (__nv_bfloat16*)p_qhi, *qlo = (__nv_bfloat16*)p_qlo;
    __nv_bfloat16 *hhi = (__nv_bfloat16*)p_hhi, *hlo = (__nv_bfloat16*)p_hlo;
    __nv_bfloat16 *muhi = (__nv_bfloat16*)p_muhi, *mulo = (__nv_bfloat16*)p_mulo;
    __nv_bfloat16 *chi = (__nv_bfloat16*)p_chi, *clo = (__nv_bfloat16*)p_clo;
    __nv_bfloat16 *Bhi = (__nv_bfloat16*)p_Bhi, *Blo = (__nv_bfloat16*)p_Blo;
    __nv_bfloat16 *FWh = (__nv_bfloat16*)p_FWh, *FWl = (__nv_bfloat16*)p_FWl;
    __nv_bfloat16 *phh = (__nv_bfloat16*)p_phh, *phl = (__nv_bfloat16*)p_phl;

    init_kernel<<<(NA * 384 + 255) / 256, 256>>>(z, embedding, q, mu);
    geom_kernel<<<(NE + 255) / 256, 256>>>(r_ij);
    fwprep_kernel<<<(NL * 384 * 32 + 255) / 256, 256>>>(filt_W, filt_b);
    wprep_kernel<<<(NL * 128 * 128 + 255) / 256, 256>>>(inter_W1, 128, 128, 0);
    wprep_kernel<<<(NL * 128 * 384 + 255) / 256, 256>>>(inter_W2, 128, 384, 16384);
    wprep_kernel<<<(NL * 128 * 256 + 255) / 256, 256>>>(mix_W, 128, 256, 65536);
    wprep_kernel<<<(NL * 256 * 128 + 255) / 256, 256>>>(intra_W1, 256, 128, 98304);
    wprep_kernel<<<(NL * 128 * 384 + 255) / 256, 256>>>(intra_W2, 128, 384, 131072);

    for (int l = 0; l < NL; l++) {
        int wb = l * WL;
        // h = silu(q @ W1 + b1) -> split only
        gemm_mma<<<dim3(1, (NA + 127) / 128), 256>>>(
            qhi, qlo, Bhi + wb, Blo + wb, inter_b1 + l * 128,
            nullptr, hhi, hlo, NA, 128, 128, 1);
        // x = h @ W2 + b2 -> fp32
        gemm_mma<<<dim3(3, (NA + 127) / 128), 256>>>(
            hhi, hlo, Bhi + wb + 16384, Blo + wb + 16384, inter_b2 + l * 384,
            xbuf, nullptr, nullptr, NA, 384, 128, 0);
        // per-edge filters via tensor GEMM: F = phi_pad(NE x 32) @ FW(384 x 32)^T
        gemm_mma<<<dim3(3, (NE + 127) / 128), 256>>>(
            phh, phl, FWh + l * 12288, FWl + l * 12288, zeros,
            filt, nullptr, nullptr, NE, 384, 32, 0);
        // edge messages (atomics into q, g_dmu)
        msg_kernel<<<2368, 128>>>(filt, idx_i, idx_j, mu, q);
        // mu += dmu (emit mu split)
        addmu_kernel<<<(NA * 192 + 255) / 256, 256>>>(mu);
        // mu_mix = mu @ mix_W + mix_b -> fp32
        gemm_mma<<<dim3(2, (NA * 3 + 127) / 128), 256>>>(
            muhi, mulo, Bhi + wb + 65536, Blo + wb + 65536, mix_b + l * 256,
            mumix, nullptr, nullptr, NA * 3, 256, 128, 0);
        // ctx = [q, ||mu_V||] -> split only
        ctx_kernel<<<(NA * 64 + 255) / 256, 256>>>(q);
        // h = silu(ctx @ intra_W1 + b1) -> split only
        gemm_mma<<<dim3(1, (NA + 127) / 128), 256>>>(
            chi, clo, Bhi + wb + 98304, Blo + wb + 98304, intra_b1 + l * 128,
            nullptr, hhi, hlo, NA, 128, 256, 1);
        // x = h @ intra_W2 + b2 -> fp32
        gemm_mma<<<dim3(3, (NA + 127) / 128), 256>>>(
            hhi, hlo, Bhi + wb + 131072, Blo + wb + 131072, intra_b2 + l * 384,
            xbuf, nullptr, nullptr, NA, 384, 128, 0);
        // q += dq_intra + dqmu_intra (emit q split); mu += dmu_intra
        update_kernel<<<(NA * 64 + 255) / 256, 256>>>(q, mu);
    }
}